// round 4
// baseline (speedup 1.0000x reference)
#include <cuda_runtime.h>
#include <math.h>

#define T_LEN 2048
#define DIM_  1024
#define NHEAD 16
#define HD    64
#define ATTN_SCALE 0.12f

// ---------------- scratch (static device memory; no allocations) ----------------
__device__ float g_q[T_LEN * DIM_];
__device__ float g_k[T_LEN * DIM_];
__device__ float g_v[T_LEN * DIM_];
__device__ float g_y[T_LEN * DIM_];

// ---------------- 128x128x16 tiled SGEMM body (M=2048, N=K=1024 hardcoded) -----
// C[M,1024] = A[M,1024] @ B[1024,1024], row-major. 256 threads, 8x8 microtile.
__device__ __forceinline__ void sgemm_body(const float* __restrict__ A,
                                           const float* __restrict__ B,
                                           float* __restrict__ C)
{
    __shared__ float As[16][128];   // transposed A tile: As[k][m]
    __shared__ float Bs[16][128];   // Bs[k][n]

    const int tid = threadIdx.x;
    const int tx  = tid & 15;       // 0..15  -> n offset tx*8
    const int ty  = tid >> 4;       // 0..15  -> m offset ty*8
    const int m0  = blockIdx.y * 128;
    const int n0  = blockIdx.x * 128;

    const int arow = tid >> 2;      // 0..63
    const int ac4  = tid & 3;       // 0..3
    const int brow = tid >> 5;      // 0..7
    const int bc4  = tid & 31;      // 0..31

    float acc[8][8];
#pragma unroll
    for (int i = 0; i < 8; i++)
#pragma unroll
        for (int j = 0; j < 8; j++) acc[i][j] = 0.0f;

    for (int k0 = 0; k0 < 1024; k0 += 16) {
#pragma unroll
        for (int s = 0; s < 2; s++) {
            int ar = arow + s * 64;
            float4 va = *(const float4*)(A + (size_t)(m0 + ar) * 1024 + k0 + ac4 * 4);
            As[ac4 * 4 + 0][ar] = va.x;
            As[ac4 * 4 + 1][ar] = va.y;
            As[ac4 * 4 + 2][ar] = va.z;
            As[ac4 * 4 + 3][ar] = va.w;
            int br = brow + s * 8;
            float4 vb = *(const float4*)(B + (size_t)(k0 + br) * 1024 + n0 + bc4 * 4);
            *(float4*)&Bs[br][bc4 * 4] = vb;
        }
        __syncthreads();

#pragma unroll
        for (int kk = 0; kk < 16; kk++) {
            float4 a0 = *(const float4*)&As[kk][ty * 8];
            float4 a1 = *(const float4*)&As[kk][ty * 8 + 4];
            float4 b0 = *(const float4*)&Bs[kk][tx * 8];
            float4 b1 = *(const float4*)&Bs[kk][tx * 8 + 4];
            float a[8] = {a0.x, a0.y, a0.z, a0.w, a1.x, a1.y, a1.z, a1.w};
            float b[8] = {b0.x, b0.y, b0.z, b0.w, b1.x, b1.y, b1.z, b1.w};
#pragma unroll
            for (int i = 0; i < 8; i++)
#pragma unroll
                for (int j = 0; j < 8; j++)
                    acc[i][j] = fmaf(a[i], b[j], acc[i][j]);
        }
        __syncthreads();
    }

#pragma unroll
    for (int i = 0; i < 8; i++) {
        float* Cp = C + (size_t)(m0 + ty * 8 + i) * 1024 + n0 + tx * 8;
        *(float4*)(Cp)     = make_float4(acc[i][0], acc[i][1], acc[i][2], acc[i][3]);
        *(float4*)(Cp + 4) = make_float4(acc[i][4], acc[i][5], acc[i][6], acc[i][7]);
    }
}

// QKV: grid.z selects which weight/output
__global__ __launch_bounds__(256) void qkv_gemm(const float* __restrict__ x,
                                                const float* __restrict__ Wq,
                                                const float* __restrict__ Wk,
                                                const float* __restrict__ Wv)
{
    const float* Bm = (blockIdx.z == 0) ? Wq : (blockIdx.z == 1) ? Wk : Wv;
    float* Cm = (blockIdx.z == 0) ? g_q : (blockIdx.z == 1) ? g_k : g_v;
    sgemm_body(x, Bm, Cm);
}

__global__ __launch_bounds__(256) void proj_gemm(const float* __restrict__ Wo,
                                                 float* __restrict__ out)
{
    sgemm_body(g_y, Wo, out);
}

// ---------------- cosine-norm + per-head scale + rotary (Q and K) ---------------
// block = 512 threads (16 warps = 16 heads), grid = T_LEN
__global__ __launch_bounds__(512) void normrope_kernel(const float* __restrict__ s_qk)
{
    const int t    = blockIdx.x;
    const int h    = threadIdx.x >> 5;
    const int lane = threadIdx.x & 31;

    // rotary tables: dim_quarter=16 real freqs, 16 zeros
    float c, s;
    if (lane < 16) {
        // freq = (1/1024)^(lane/15) computed in double, rounded to fp32 like jnp
        double fr = exp((double)lane * (-6.931471805599453 / 15.0));
        float  freqf = (float)fr;
        float  theta = (float)t * freqf;
        sincosf(theta, &s, &c);
    } else {
        c = 1.0f; s = 0.0f;
    }

    const float sc1 = s_qk[h * HD + lane]      * 32.0f;  // sqrt(1024)=32
    const float sc2 = s_qk[h * HD + lane + 32] * 32.0f;

    float* ptrs[2] = {g_q + (size_t)t * DIM_ + h * HD,
                      g_k + (size_t)t * DIM_ + h * HD};
#pragma unroll
    for (int w = 0; w < 2; w++) {
        float* p = ptrs[w];
        float v1 = p[lane];
        float v2 = p[lane + 32];
        float ss = v1 * v1 + v2 * v2;
#pragma unroll
        for (int o = 16; o > 0; o >>= 1)
            ss += __shfl_xor_sync(0xffffffffu, ss, o);
        float rn = rsqrtf(ss + 1e-12f);
        v1 *= rn * sc1;
        v2 *= rn * sc2;
        // rotary on pair (lane, lane+32)
        float y1 = v1 * c + v2 * s;
        float y2 = v2 * c - v1 * s;
        p[lane]      = y1;
        p[lane + 32] = y2;
    }
}

// ---------------- flash-style causal attention ----------------------------------
// grid = (32 query-blocks, 16 heads), 256 threads, 64 queries/block, online softmax
#define SMEM_ATTN_FLOATS (4 * 64 * 65 + 3 * 64)
__global__ __launch_bounds__(256) void attn_kernel()
{
    extern __shared__ float sm[];
    float* QsT  = sm;                 // [64 feat][65]  (feature-major, padded)
    float* KsT  = sm + 4160;          // [64 feat][65]
    float* Vs   = sm + 2 * 4160;      // [64 key ][65]
    float* Ss   = sm + 3 * 4160;      // [64 q   ][65]
    float* m_s  = sm + 4 * 4160;
    float* l_s  = m_s + 64;
    float* cr_s = l_s + 64;

    const int qb  = 31 - (int)blockIdx.x;   // heavy blocks launch first
    const int h   = blockIdx.y;
    const int tid = threadIdx.x;
    const int tx  = tid & 15;
    const int ty  = tid >> 4;
    const int qi0 = ty * 4;
    const int dj0 = tx * 4;

    const float* Qg = g_q + (size_t)(qb * 64) * DIM_ + h * HD;
    float*       Yg = g_y + (size_t)(qb * 64) * DIM_ + h * HD;

    // load Q tile transposed (coalesced global, conflict-free smem stores)
    for (int p = tid; p < 4096; p += 256) {
        int r = p >> 6, cc = p & 63;
        QsT[cc * 65 + r] = Qg[(size_t)r * DIM_ + cc];
    }
    if (tid < 64) { m_s[tid] = -1e30f; l_s[tid] = 0.0f; }

    float acc[4][4];
#pragma unroll
    for (int i = 0; i < 4; i++)
#pragma unroll
        for (int j = 0; j < 4; j++) acc[i][j] = 0.0f;

    for (int kb = 0; kb <= qb; kb++) {
        const float* Kg = g_k + (size_t)(kb * 64) * DIM_ + h * HD;
        const float* Vg = g_v + (size_t)(kb * 64) * DIM_ + h * HD;

        __syncthreads();  // previous iter done with Ss/Vs/KsT (also covers Q load)
        for (int p = tid; p < 4096; p += 256) {
            int r = p >> 6, cc = p & 63;
            KsT[cc * 65 + r] = Kg[(size_t)r * DIM_ + cc];
            Vs[r * 65 + cc]  = Vg[(size_t)r * DIM_ + cc];
        }
        __syncthreads();

        // S = (Q K^T) * scale   (thread owns S[qi0+i][tx*4+j])
        float sv[4][4];
#pragma unroll
        for (int i = 0; i < 4; i++)
#pragma unroll
            for (int j = 0; j < 4; j++) sv[i][j] = 0.0f;

#pragma unroll 8
        for (int kk = 0; kk < 64; kk++) {
            float a0 = QsT[kk * 65 + qi0 + 0];
            float a1 = QsT[kk * 65 + qi0 + 1];
            float a2 = QsT[kk * 65 + qi0 + 2];
            float a3 = QsT[kk * 65 + qi0 + 3];
            float b0 = KsT[kk * 65 + dj0 + 0];
            float b1 = KsT[kk * 65 + dj0 + 1];
            float b2 = KsT[kk * 65 + dj0 + 2];
            float b3 = KsT[kk * 65 + dj0 + 3];
            sv[0][0] = fmaf(a0, b0, sv[0][0]); sv[0][1] = fmaf(a0, b1, sv[0][1]);
            sv[0][2] = fmaf(a0, b2, sv[0][2]); sv[0][3] = fmaf(a0, b3, sv[0][3]);
            sv[1][0] = fmaf(a1, b0, sv[1][0]); sv[1][1] = fmaf(a1, b1, sv[1][1]);
            sv[1][2] = fmaf(a1, b2, sv[1][2]); sv[1][3] = fmaf(a1, b3, sv[1][3]);
            sv[2][0] = fmaf(a2, b0, sv[2][0]); sv[2][1] = fmaf(a2, b1, sv[2][1]);
            sv[2][2] = fmaf(a2, b2, sv[2][2]); sv[2][3] = fmaf(a2, b3, sv[2][3]);
            sv[3][0] = fmaf(a3, b0, sv[3][0]); sv[3][1] = fmaf(a3, b1, sv[3][1]);
            sv[3][2] = fmaf(a3, b2, sv[3][2]); sv[3][3] = fmaf(a3, b3, sv[3][3]);
        }

        const bool diag = (kb == qb);
#pragma unroll
        for (int i = 0; i < 4; i++)
#pragma unroll
            for (int j = 0; j < 4; j++) {
                float val = sv[i][j] * ATTN_SCALE;
                if (diag && (dj0 + j) > (qi0 + i)) val = -1e30f;
                Ss[(qi0 + i) * 65 + dj0 + j] = val;
            }
        __syncthreads();

        // online softmax update: 4 threads per row
        {
            const int row = tid >> 2, pp = tid & 3;
            float mloc = -1e30f;
#pragma unroll
            for (int cc = 0; cc < 16; cc++)
                mloc = fmaxf(mloc, Ss[row * 65 + pp * 16 + cc]);
            mloc = fmaxf(mloc, __shfl_xor_sync(0xffffffffu, mloc, 1));
            mloc = fmaxf(mloc, __shfl_xor_sync(0xffffffffu, mloc, 2));
            float mold = m_s[row];
            float mnew = fmaxf(mold, mloc);
            float sloc = 0.0f;
#pragma unroll
            for (int cc = 0; cc < 16; cc++) {
                float e = __expf(Ss[row * 65 + pp * 16 + cc] - mnew);
                Ss[row * 65 + pp * 16 + cc] = e;
                sloc += e;
            }
            sloc += __shfl_xor_sync(0xffffffffu, sloc, 1);
            sloc += __shfl_xor_sync(0xffffffffu, sloc, 2);
            if (pp == 0) {
                float corr = __expf(mold - mnew);
                l_s[row]  = l_s[row] * corr + sloc;
                m_s[row]  = mnew;
                cr_s[row] = corr;
            }
        }
        __syncthreads();

        // rescale + O += P @ V   (thread owns O[qi0+i][dj0+j])
        float cri[4] = {cr_s[qi0 + 0], cr_s[qi0 + 1], cr_s[qi0 + 2], cr_s[qi0 + 3]};
#pragma unroll
        for (int i = 0; i < 4; i++)
#pragma unroll
            for (int j = 0; j < 4; j++) acc[i][j] *= cri[i];

#pragma unroll 8
        for (int kk = 0; kk < 64; kk++) {
            float b0 = Vs[kk * 65 + dj0 + 0];
            float b1 = Vs[kk * 65 + dj0 + 1];
            float b2 = Vs[kk * 65 + dj0 + 2];
            float b3 = Vs[kk * 65 + dj0 + 3];
            float p0 = Ss[(qi0 + 0) * 65 + kk];
            float p1 = Ss[(qi0 + 1) * 65 + kk];
            float p2 = Ss[(qi0 + 2) * 65 + kk];
            float p3 = Ss[(qi0 + 3) * 65 + kk];
            acc[0][0] = fmaf(p0, b0, acc[0][0]); acc[0][1] = fmaf(p0, b1, acc[0][1]);
            acc[0][2] = fmaf(p0, b2, acc[0][2]); acc[0][3] = fmaf(p0, b3, acc[0][3]);
            acc[1][0] = fmaf(p1, b0, acc[1][0]); acc[1][1] = fmaf(p1, b1, acc[1][1]);
            acc[1][2] = fmaf(p1, b2, acc[1][2]); acc[1][3] = fmaf(p1, b3, acc[1][3]);
            acc[2][0] = fmaf(p2, b0, acc[2][0]); acc[2][1] = fmaf(p2, b1, acc[2][1]);
            acc[2][2] = fmaf(p2, b2, acc[2][2]); acc[2][3] = fmaf(p2, b3, acc[2][3]);
            acc[3][0] = fmaf(p3, b0, acc[3][0]); acc[3][1] = fmaf(p3, b1, acc[3][1]);
            acc[3][2] = fmaf(p3, b2, acc[3][2]); acc[3][3] = fmaf(p3, b3, acc[3][3]);
        }
    }

    // epilogue: O /= l
#pragma unroll
    for (int i = 0; i < 4; i++) {
        float inv = 1.0f / l_s[qi0 + i];
#pragma unroll
        for (int j = 0; j < 4; j++)
            Yg[(size_t)(qi0 + i) * DIM_ + dj0 + j] = acc[i][j] * inv;
    }
}

// ---------------- launcher ------------------------------------------------------
extern "C" void kernel_launch(void* const* d_in, const int* in_sizes, int n_in,
                              void* d_out, int out_size)
{
    const float* x    = (const float*)d_in[0];
    const float* Wq   = (const float*)d_in[1];
    const float* Wk   = (const float*)d_in[2];
    const float* Wv   = (const float*)d_in[3];
    const float* Wo   = (const float*)d_in[4];
    const float* s_qk = (const float*)d_in[5];
    float* out = (float*)d_out;

    const size_t attn_smem = SMEM_ATTN_FLOATS * sizeof(float);  // 67,328 B
    cudaFuncSetAttribute(attn_kernel, cudaFuncAttributeMaxDynamicSharedMemorySize,
                         (int)attn_smem);

    dim3 gqkv(1024 / 128, 2048 / 128, 3);
    qkv_gemm<<<gqkv, 256>>>(x, Wq, Wk, Wv);

    normrope_kernel<<<T_LEN, 512>>>(s_qk);

    attn_kernel<<<dim3(32, NHEAD), 256, attn_smem>>>();

    dim3 gproj(1024 / 128, 2048 / 128);
    proj_gemm<<<gproj, 256>>>(Wo, out);
}

// round 6
// speedup vs baseline: 1.3984x; 1.3984x over previous
#include <cuda_runtime.h>
#include <cuda_bf16.h>
#include <mma.h>
#include <math.h>
#include <stdint.h>

using namespace nvcuda;

#define T_LEN 2048
#define DIM_  1024
#define NHEAD 16
#define HD    64
#define ATTN_SCALE 0.12f

// ---------------- scratch (static device memory; no allocations) ----------------
__device__ float g_q[T_LEN * DIM_];
__device__ float g_k[T_LEN * DIM_];
__device__ float g_v[T_LEN * DIM_];
__device__ float g_y[T_LEN * DIM_];
// split-bf16 operands: [.,0:1024)=hi, [.,1024:2048)=lo
__device__ __nv_bfloat16 g_abig[T_LEN * 2048];           // split(x)
__device__ __nv_bfloat16 g_ybig[T_LEN * 2048];           // split(y)
__device__ __nv_bfloat16 g_wt[4][1024 * 2048];           // split(W^T), [n][k] K-major

// ---------------- split conversion (x or y -> hi|lo bf16) -----------------------
__global__ __launch_bounds__(256) void split_kernel(const float* __restrict__ xin, int which)
{
    const float* in = which ? g_y : xin;
    __nv_bfloat16* outp = which ? g_ybig : g_abig;
    int idx = blockIdx.x * 256 + threadIdx.x;          // over 2048*1024/4 float4s
    float4 v = ((const float4*)in)[idx];
    int m  = idx >> 8;
    int c0 = (idx & 255) << 2;
    __nv_bfloat16 h0 = __float2bfloat16(v.x), h1 = __float2bfloat16(v.y);
    __nv_bfloat16 h2 = __float2bfloat16(v.z), h3 = __float2bfloat16(v.w);
    __nv_bfloat16 l0 = __float2bfloat16(v.x - __bfloat162float(h0));
    __nv_bfloat16 l1 = __float2bfloat16(v.y - __bfloat162float(h1));
    __nv_bfloat16 l2 = __float2bfloat16(v.z - __bfloat162float(h2));
    __nv_bfloat16 l3 = __float2bfloat16(v.w - __bfloat162float(h3));
    __nv_bfloat16* po = outp + (size_t)m * 2048 + c0;
    po[0] = h0; po[1] = h1; po[2] = h2; po[3] = h3;
    po[1024] = l0; po[1025] = l1; po[1026] = l2; po[1027] = l3;
}

// ---------------- weight transpose + split: W[k][n] -> WT[n][k_hi | k_lo] -------
__global__ __launch_bounds__(256) void wconv_kernel(const float* __restrict__ Wq,
                                                    const float* __restrict__ Wk,
                                                    const float* __restrict__ Wv,
                                                    const float* __restrict__ Wo)
{
    __shared__ float tile[32][33];
    const int z = blockIdx.z;
    const float* W = (z == 0) ? Wq : (z == 1) ? Wk : (z == 2) ? Wv : Wo;
    __nv_bfloat16* WT = g_wt[z];
    const int tx = threadIdx.x & 31, ty = threadIdx.x >> 5;   // (32, 8)
    const int n  = blockIdx.x * 32 + tx;
    const int k0 = blockIdx.y * 32;
#pragma unroll
    for (int i = 0; i < 4; i++)
        tile[ty + i * 8][tx] = W[(size_t)(k0 + ty + i * 8) * 1024 + n];
    __syncthreads();
#pragma unroll
    for (int i = 0; i < 4; i++) {
        float v = tile[tx][ty + i * 8];
        __nv_bfloat16 hi = __float2bfloat16(v);
        __nv_bfloat16 lo = __float2bfloat16(v - __bfloat162float(hi));
        size_t base = (size_t)(blockIdx.x * 32 + ty + i * 8) * 2048 + k0 + tx;
        WT[base]        = hi;
        WT[base + 1024] = lo;
    }
}

// ---------------- WMMA split-bf16 GEMM: C[2048,1024] = A' @ W'^T ----------------
// Logical K'=3072 via 48 chunks of 64: part0 = A_hi*W_hi, part1 = A_hi*W_lo,
// part2 = A_lo*W_hi. 128x128 CTA tile, 8 warps (4m x 2n), warp tile 32x64.
// Double-buffered smem, global->reg prefetch overlapped with WMMA compute.
#define GEMM_NCHUNK 48
#define SLD 72                                   // smem leading dim (elements)
#define ABUF (128 * SLD)                         // elements per A (or B) tile
#define GEMM_SMEM (2 * 2 * ABUF * 2)             // 2 bufs x (A+B) x 2 bytes = 73728

__global__ __launch_bounds__(256) void gemm_wmma(int proj, float* __restrict__ outp)
{
    extern __shared__ __nv_bfloat16 smb[];
    const int tid = threadIdx.x;
    const int wid = tid >> 5;
    const int n0 = blockIdx.x * 128;
    const int m0 = blockIdx.y * 128;
    const int z  = blockIdx.z;

    const __nv_bfloat16* A  = proj ? g_ybig : g_abig;
    const __nv_bfloat16* Bt = proj ? g_wt[3] : g_wt[z];
    float* C = proj ? outp : (z == 0 ? g_q : z == 1 ? g_k : g_v);

    const __nv_bfloat16* Ag = A  + (size_t)m0 * 2048;
    const __nv_bfloat16* Bg = Bt + (size_t)n0 * 2048;

    const int wm = wid >> 1;          // 0..3 -> m offset wm*32
    const int wn = wid & 1;           // 0..1 -> n offset wn*64

    wmma::fragment<wmma::accumulator, 16, 16, 16, float> acc[2][4];
#pragma unroll
    for (int i = 0; i < 2; i++)
#pragma unroll
        for (int j = 0; j < 4; j++) wmma::fill_fragment(acc[i][j], 0.0f);

    // per-thread load slots: 4 uint4 for A tile, 4 for B tile (1024 uint4 each)
    const int r0 = tid >> 3;          // base row for slot s: r0 + s*32
    const int c8 = (tid & 7) * 8;     // element offset within 64-wide row

    uint4 ra[4], rb[4];
    // ---- preload chunk 0 (part 0: hi/hi, ka=kb=0) ----
#pragma unroll
    for (int s = 0; s < 4; s++) {
        int row = r0 + s * 32;
        ra[s] = *(const uint4*)(Ag + (size_t)row * 2048 + c8);
        rb[s] = *(const uint4*)(Bg + (size_t)row * 2048 + c8);
    }
    {
        __nv_bfloat16* As = smb;
        __nv_bfloat16* Bs = smb + ABUF;
#pragma unroll
        for (int s = 0; s < 4; s++) {
            int row = r0 + s * 32;
            *(uint4*)(As + row * SLD + c8) = ra[s];
            *(uint4*)(Bs + row * SLD + c8) = rb[s];
        }
    }
    __syncthreads();

    for (int c = 0; c < GEMM_NCHUNK; c++) {
        // prefetch chunk c+1 into registers (overlaps with compute below)
        if (c + 1 < GEMM_NCHUNK) {
            const int cn = c + 1;
            const int part = cn >> 4, sub = cn & 15;
            const int ka = (part == 2 ? 1024 : 0) + sub * 64;   // A: hi,hi,lo
            const int kb = (part == 1 ? 1024 : 0) + sub * 64;   // B: hi,lo,hi
#pragma unroll
            for (int s = 0; s < 4; s++) {
                int row = r0 + s * 32;
                ra[s] = *(const uint4*)(Ag + (size_t)row * 2048 + ka + c8);
                rb[s] = *(const uint4*)(Bg + (size_t)row * 2048 + kb + c8);
            }
        }

        // compute on buffer c&1
        {
            const __nv_bfloat16* As = smb + (c & 1) * 2 * ABUF;
            const __nv_bfloat16* Bs = As + ABUF;
#pragma unroll
            for (int kk = 0; kk < 4; kk++) {
                const int k = kk * 16;
                wmma::fragment<wmma::matrix_a, 16, 16, 16, __nv_bfloat16, wmma::row_major> af[2];
                wmma::fragment<wmma::matrix_b, 16, 16, 16, __nv_bfloat16, wmma::col_major> bf[4];
                wmma::load_matrix_sync(af[0], As + (wm * 32 +  0) * SLD + k, SLD);
                wmma::load_matrix_sync(af[1], As + (wm * 32 + 16) * SLD + k, SLD);
#pragma unroll
                for (int j = 0; j < 4; j++)
                    wmma::load_matrix_sync(bf[j], Bs + (wn * 64 + j * 16) * SLD + k, SLD);
#pragma unroll
                for (int i = 0; i < 2; i++)
#pragma unroll
                    for (int j = 0; j < 4; j++)
                        wmma::mma_sync(acc[i][j], af[i], bf[j], acc[i][j]);
            }
        }

        // store prefetched regs into the other buffer
        if (c + 1 < GEMM_NCHUNK) {
            __nv_bfloat16* As = smb + ((c + 1) & 1) * 2 * ABUF;
            __nv_bfloat16* Bs = As + ABUF;
#pragma unroll
            for (int s = 0; s < 4; s++) {
                int row = r0 + s * 32;
                *(uint4*)(As + row * SLD + c8) = ra[s];
                *(uint4*)(Bs + row * SLD + c8) = rb[s];
            }
        }
        __syncthreads();
    }

    // epilogue: accumulators -> C (fp32, row-major)
#pragma unroll
    for (int i = 0; i < 2; i++)
#pragma unroll
        for (int j = 0; j < 4; j++)
            wmma::store_matrix_sync(
                C + (size_t)(m0 + wm * 32 + i * 16) * 1024 + n0 + wn * 64 + j * 16,
                acc[i][j], 1024, wmma::mem_row_major);
}

// ---------------- cosine-norm + per-head scale + rotary (Q and K) ---------------
__global__ __launch_bounds__(512) void normrope_kernel(const float* __restrict__ s_qk)
{
    const int t    = blockIdx.x;
    const int h    = threadIdx.x >> 5;
    const int lane = threadIdx.x & 31;

    float c, s;
    if (lane < 16) {
        double fr = exp((double)lane * (-6.931471805599453 / 15.0));
        float theta = (float)t * (float)fr;
        sincosf(theta, &s, &c);
    } else { c = 1.0f; s = 0.0f; }

    const float sc1 = s_qk[h * HD + lane]      * 32.0f;
    const float sc2 = s_qk[h * HD + lane + 32] * 32.0f;

    float* ptrs[2] = {g_q + (size_t)t * DIM_ + h * HD,
                      g_k + (size_t)t * DIM_ + h * HD};
#pragma unroll
    for (int w = 0; w < 2; w++) {
        float* p = ptrs[w];
        float v1 = p[lane];
        float v2 = p[lane + 32];
        float ss = v1 * v1 + v2 * v2;
#pragma unroll
        for (int o = 16; o > 0; o >>= 1)
            ss += __shfl_xor_sync(0xffffffffu, ss, o);
        float rn = rsqrtf(ss + 1e-12f);
        v1 *= rn * sc1;
        v2 *= rn * sc2;
        float y1 = v1 * c + v2 * s;
        float y2 = v2 * c - v1 * s;
        p[lane]      = y1;
        p[lane + 32] = y2;
    }
}

// ---------------- flash-style causal attention (unchanged, passing) -------------
#define SMEM_ATTN_FLOATS (4 * 64 * 65 + 3 * 64)
__global__ __launch_bounds__(256) void attn_kernel()
{
    extern __shared__ float sm[];
    float* QsT  = sm;
    float* KsT  = sm + 4160;
    float* Vs   = sm + 2 * 4160;
    float* Ss   = sm + 3 * 4160;
    float* m_s  = sm + 4 * 4160;
    float* l_s  = m_s + 64;
    float* cr_s = l_s + 64;

    const int qb  = 31 - (int)blockIdx.x;
    const int h   = blockIdx.y;
    const int tid = threadIdx.x;
    const int tx  = tid & 15;
    const int ty  = tid >> 4;
    const int qi0 = ty * 4;
    const int dj0 = tx * 4;

    const float* Qg = g_q + (size_t)(qb * 64) * DIM_ + h * HD;
    float*       Yg = g_y + (size_t)(qb * 64) * DIM_ + h * HD;

    for (int p = tid; p < 4096; p += 256) {
        int r = p >> 6, cc = p & 63;
        QsT[cc * 65 + r] = Qg[(size_t)r * DIM_ + cc];
    }
    if (tid < 64) { m_s[tid] = -1e30f; l_s[tid] = 0.0f; }

    float acc[4][4];
#pragma unroll
    for (int i = 0; i < 4; i++)
#pragma unroll
        for (int j = 0; j < 4; j++) acc[i][j] = 0.0f;

    for (int kb = 0; kb <= qb; kb++) {
        const float* Kg = g_k + (size_t)(kb * 64) * DIM_ + h * HD;
        const float* Vg = g_v + (size_t)(kb * 64) * DIM_ + h * HD;

        __syncthreads();
        for (int p = tid; p < 4096; p += 256) {
            int r = p >> 6, cc = p & 63;
            KsT[cc * 65 + r] = Kg[(size_t)r * DIM_ + cc];
            Vs[r * 65 + cc]  = Vg[(size_t)r * DIM_ + cc];
        }
        __syncthreads();

        float sv[4][4];
#pragma unroll
        for (int i = 0; i < 4; i++)
#pragma unroll
            for (int j = 0; j < 4; j++) sv[i][j] = 0.0f;

#pragma unroll 8
        for (int kk = 0; kk < 64; kk++) {
            float a0 = QsT[kk * 65 + qi0 + 0];
            float a1 = QsT[kk * 65 + qi0 + 1];
            float a2 = QsT[kk * 65 + qi0 + 2];
            float a3 = QsT[kk * 65 + qi0 + 3];
            float b0 = KsT[kk * 65 + dj0 + 0];
            float b1 = KsT[kk * 65 + dj0 + 1];
            float b2 = KsT[kk * 65 + dj0 + 2];
            float b3 = KsT[kk * 65 + dj0 + 3];
            sv[0][0] = fmaf(a0, b0, sv[0][0]); sv[0][1] = fmaf(a0, b1, sv[0][1]);
            sv[0][2] = fmaf(a0, b2, sv[0][2]); sv[0][3] = fmaf(a0, b3, sv[0][3]);
            sv[1][0] = fmaf(a1, b0, sv[1][0]); sv[1][1] = fmaf(a1, b1, sv[1][1]);
            sv[1][2] = fmaf(a1, b2, sv[1][2]); sv[1][3] = fmaf(a1, b3, sv[1][3]);
            sv[2][0] = fmaf(a2, b0, sv[2][0]); sv[2][1] = fmaf(a2, b1, sv[2][1]);
            sv[2][2] = fmaf(a2, b2, sv[2][2]); sv[2][3] = fmaf(a2, b3, sv[2][3]);
            sv[3][0] = fmaf(a3, b0, sv[3][0]); sv[3][1] = fmaf(a3, b1, sv[3][1]);
            sv[3][2] = fmaf(a3, b2, sv[3][2]); sv[3][3] = fmaf(a3, b3, sv[3][3]);
        }

        const bool diag = (kb == qb);
#pragma unroll
        for (int i = 0; i < 4; i++)
#pragma unroll
            for (int j = 0; j < 4; j++) {
                float val = sv[i][j] * ATTN_SCALE;
                if (diag && (dj0 + j) > (qi0 + i)) val = -1e30f;
                Ss[(qi0 + i) * 65 + dj0 + j] = val;
            }
        __syncthreads();

        {
            const int row = tid >> 2, pp = tid & 3;
            float mloc = -1e30f;
#pragma unroll
            for (int cc = 0; cc < 16; cc++)
                mloc = fmaxf(mloc, Ss[row * 65 + pp * 16 + cc]);
            mloc = fmaxf(mloc, __shfl_xor_sync(0xffffffffu, mloc, 1));
            mloc = fmaxf(mloc, __shfl_xor_sync(0xffffffffu, mloc, 2));
            float mold = m_s[row];
            float mnew = fmaxf(mold, mloc);
            float sloc = 0.0f;
#pragma unroll
            for (int cc = 0; cc < 16; cc++) {
                float e = __expf(Ss[row * 65 + pp * 16 + cc] - mnew);
                Ss[row * 65 + pp * 16 + cc] = e;
                sloc += e;
            }
            sloc += __shfl_xor_sync(0xffffffffu, sloc, 1);
            sloc += __shfl_xor_sync(0xffffffffu, sloc, 2);
            if (pp == 0) {
                float corr = __expf(mold - mnew);
                l_s[row]  = l_s[row] * corr + sloc;
                m_s[row]  = mnew;
                cr_s[row] = corr;
            }
        }
        __syncthreads();

        float cri[4] = {cr_s[qi0 + 0], cr_s[qi0 + 1], cr_s[qi0 + 2], cr_s[qi0 + 3]};
#pragma unroll
        for (int i = 0; i < 4; i++)
#pragma unroll
            for (int j = 0; j < 4; j++) acc[i][j] *= cri[i];

#pragma unroll 8
        for (int kk = 0; kk < 64; kk++) {
            float b0 = Vs[kk * 65 + dj0 + 0];
            float b1 = Vs[kk * 65 + dj0 + 1];
            float b2 = Vs[kk * 65 + dj0 + 2];
            float b3 = Vs[kk * 65 + dj0 + 3];
            float p0 = Ss[(qi0 + 0) * 65 + kk];
            float p1 = Ss[(qi0 + 1) * 65 + kk];
            float p2 = Ss[(qi0 + 2) * 65 + kk];
            float p3 = Ss[(qi0 + 3) * 65 + kk];
            acc[0][0] = fmaf(p0, b0, acc[0][0]); acc[0][1] = fmaf(p0, b1, acc[0][1]);
            acc[0][2] = fmaf(p0, b2, acc[0][2]); acc[0][3] = fmaf(p0, b3, acc[0][3]);
            acc[1][0] = fmaf(p1, b0, acc[1][0]); acc[1][1] = fmaf(p1, b1, acc[1][1]);
            acc[1][2] = fmaf(p1, b2, acc[1][2]); acc[1][3] = fmaf(p1, b3, acc[1][3]);
            acc[2][0] = fmaf(p2, b0, acc[2][0]); acc[2][1] = fmaf(p2, b1, acc[2][1]);
            acc[2][2] = fmaf(p2, b2, acc[2][2]); acc[2][3] = fmaf(p2, b3, acc[2][3]);
            acc[3][0] = fmaf(p3, b0, acc[3][0]); acc[3][1] = fmaf(p3, b1, acc[3][1]);
            acc[3][2] = fmaf(p3, b2, acc[3][2]); acc[3][3] = fmaf(p3, b3, acc[3][3]);
        }
    }

#pragma unroll
    for (int i = 0; i < 4; i++) {
        float inv = 1.0f / l_s[qi0 + i];
#pragma unroll
        for (int j = 0; j < 4; j++)
            Yg[(size_t)(qi0 + i) * DIM_ + dj0 + j] = acc[i][j] * inv;
    }
}

// ---------------- launcher ------------------------------------------------------
extern "C" void kernel_launch(void* const* d_in, const int* in_sizes, int n_in,
                              void* d_out, int out_size)
{
    const float* x    = (const float*)d_in[0];
    const float* Wq   = (const float*)d_in[1];
    const float* Wk   = (const float*)d_in[2];
    const float* Wv   = (const float*)d_in[3];
    const float* Wo   = (const float*)d_in[4];
    const float* s_qk = (const float*)d_in[5];
    float* out = (float*)d_out;

    const size_t attn_smem = SMEM_ATTN_FLOATS * sizeof(float);
    cudaFuncSetAttribute(attn_kernel, cudaFuncAttributeMaxDynamicSharedMemorySize,
                         (int)attn_smem);
    cudaFuncSetAttribute(gemm_wmma, cudaFuncAttributeMaxDynamicSharedMemorySize,
                         GEMM_SMEM);

    // operand prep
    split_kernel<<<2048, 256>>>(x, 0);
    wconv_kernel<<<dim3(32, 32, 4), 256>>>(Wq, Wk, Wv, Wo);

    // QKV projections (split-bf16 WMMA, logical K'=3072)
    gemm_wmma<<<dim3(8, 16, 3), 256, GEMM_SMEM>>>(0, nullptr);

    normrope_kernel<<<T_LEN, 512>>>(s_qk);

    attn_kernel<<<dim3(32, NHEAD), 256, attn_smem>>>();

    // output projection
    split_kernel<<<2048, 256>>>(nullptr, 1);
    gemm_wmma<<<dim3(8, 16, 1), 256, GEMM_SMEM>>>(1, out);
}

// round 7
// speedup vs baseline: 1.9938x; 1.4258x over previous
#include <cuda_runtime.h>
#include <cuda_bf16.h>
#include <mma.h>
#include <math.h>
#include <stdint.h>

using namespace nvcuda;

#define T_LEN 2048
#define DIM_  1024
#define NHEAD 16
#define HD    64
#define ATTN_SCALE 0.12f

// ---------------- scratch (static device memory; no allocations) ----------------
__device__ float g_q[T_LEN * DIM_];
__device__ float g_k[T_LEN * DIM_];
__device__ float g_v[T_LEN * DIM_];
__device__ float g_y[T_LEN * DIM_];
// split-bf16 operands for GEMMs: [.,0:1024)=hi, [.,1024:2048)=lo
__device__ __nv_bfloat16 g_abig[T_LEN * 2048];           // split(x)
__device__ __nv_bfloat16 g_ybig[T_LEN * 2048];           // split(y)
__device__ __nv_bfloat16 g_wt[4][1024 * 2048];           // split(W^T), [n][k] K-major
// split-bf16 q/k/v for attention (post norm+rope), layout [t][1024]
__device__ __nv_bfloat16 g_qh[T_LEN * DIM_], g_ql[T_LEN * DIM_];
__device__ __nv_bfloat16 g_kh[T_LEN * DIM_], g_kl[T_LEN * DIM_];
__device__ __nv_bfloat16 g_vh[T_LEN * DIM_], g_vl[T_LEN * DIM_];

// rotary freqs (fp32 of 2^(-2i/3), matches (1/1024)^(i/15) computed in double)
__constant__ float FREQ16[16] = {
    1.0f, 0.6299605249474366f, 0.3968502629920499f, 0.25f,
    0.15749013123685915f, 0.09921256574801247f, 0.0625f, 0.03937253280921479f,
    0.024803141437003118f, 0.015625f, 0.009843133202303698f, 0.0062007853592507794f,
    0.00390625f, 0.0024607833005759246f, 0.0015501963398126949f, 0.0009765625f
};

// ---------------- split conversion (x or y -> hi|lo bf16) -----------------------
__global__ __launch_bounds__(256) void split_kernel(const float* __restrict__ xin, int which)
{
    const float* in = which ? g_y : xin;
    __nv_bfloat16* outp = which ? g_ybig : g_abig;
    int idx = blockIdx.x * 256 + threadIdx.x;
    float4 v = ((const float4*)in)[idx];
    int m  = idx >> 8;
    int c0 = (idx & 255) << 2;
    __nv_bfloat16 h0 = __float2bfloat16(v.x), h1 = __float2bfloat16(v.y);
    __nv_bfloat16 h2 = __float2bfloat16(v.z), h3 = __float2bfloat16(v.w);
    __nv_bfloat16 l0 = __float2bfloat16(v.x - __bfloat162float(h0));
    __nv_bfloat16 l1 = __float2bfloat16(v.y - __bfloat162float(h1));
    __nv_bfloat16 l2 = __float2bfloat16(v.z - __bfloat162float(h2));
    __nv_bfloat16 l3 = __float2bfloat16(v.w - __bfloat162float(h3));
    __nv_bfloat16* po = outp + (size_t)m * 2048 + c0;
    po[0] = h0; po[1] = h1; po[2] = h2; po[3] = h3;
    po[1024] = l0; po[1025] = l1; po[1026] = l2; po[1027] = l3;
}

// ---------------- weight transpose + split: W[k][n] -> WT[n][k_hi | k_lo] -------
__global__ __launch_bounds__(256) void wconv_kernel(const float* __restrict__ Wq,
                                                    const float* __restrict__ Wk,
                                                    const float* __restrict__ Wv,
                                                    const float* __restrict__ Wo)
{
    __shared__ float tile[32][33];
    const int z = blockIdx.z;
    const float* W = (z == 0) ? Wq : (z == 1) ? Wk : (z == 2) ? Wv : Wo;
    __nv_bfloat16* WT = g_wt[z];
    const int tx = threadIdx.x & 31, ty = threadIdx.x >> 5;
    const int n  = blockIdx.x * 32 + tx;
    const int k0 = blockIdx.y * 32;
#pragma unroll
    for (int i = 0; i < 4; i++)
        tile[ty + i * 8][tx] = W[(size_t)(k0 + ty + i * 8) * 1024 + n];
    __syncthreads();
#pragma unroll
    for (int i = 0; i < 4; i++) {
        float v = tile[tx][ty + i * 8];
        __nv_bfloat16 hi = __float2bfloat16(v);
        __nv_bfloat16 lo = __float2bfloat16(v - __bfloat162float(hi));
        size_t base = (size_t)(blockIdx.x * 32 + ty + i * 8) * 2048 + k0 + tx;
        WT[base]        = hi;
        WT[base + 1024] = lo;
    }
}

// ---------------- WMMA split-bf16 GEMM (unchanged from R6, passing) -------------
#define GEMM_NCHUNK 48
#define SLD 72
#define ABUF (128 * SLD)
#define GEMM_SMEM (2 * 2 * ABUF * 2)

__global__ __launch_bounds__(256) void gemm_wmma(int proj, float* __restrict__ outp)
{
    extern __shared__ __nv_bfloat16 smb[];
    const int tid = threadIdx.x;
    const int wid = tid >> 5;
    const int n0 = blockIdx.x * 128;
    const int m0 = blockIdx.y * 128;
    const int z  = blockIdx.z;

    const __nv_bfloat16* A  = proj ? g_ybig : g_abig;
    const __nv_bfloat16* Bt = proj ? g_wt[3] : g_wt[z];
    float* C = proj ? outp : (z == 0 ? g_q : z == 1 ? g_k : g_v);

    const __nv_bfloat16* Ag = A  + (size_t)m0 * 2048;
    const __nv_bfloat16* Bg = Bt + (size_t)n0 * 2048;

    const int wm = wid >> 1;
    const int wn = wid & 1;

    wmma::fragment<wmma::accumulator, 16, 16, 16, float> acc[2][4];
#pragma unroll
    for (int i = 0; i < 2; i++)
#pragma unroll
        for (int j = 0; j < 4; j++) wmma::fill_fragment(acc[i][j], 0.0f);

    const int r0 = tid >> 3;
    const int c8 = (tid & 7) * 8;

    uint4 ra[4], rb[4];
#pragma unroll
    for (int s = 0; s < 4; s++) {
        int row = r0 + s * 32;
        ra[s] = *(const uint4*)(Ag + (size_t)row * 2048 + c8);
        rb[s] = *(const uint4*)(Bg + (size_t)row * 2048 + c8);
    }
    {
        __nv_bfloat16* As = smb;
        __nv_bfloat16* Bs = smb + ABUF;
#pragma unroll
        for (int s = 0; s < 4; s++) {
            int row = r0 + s * 32;
            *(uint4*)(As + row * SLD + c8) = ra[s];
            *(uint4*)(Bs + row * SLD + c8) = rb[s];
        }
    }
    __syncthreads();

    for (int c = 0; c < GEMM_NCHUNK; c++) {
        if (c + 1 < GEMM_NCHUNK) {
            const int cn = c + 1;
            const int part = cn >> 4, sub = cn & 15;
            const int ka = (part == 2 ? 1024 : 0) + sub * 64;
            const int kb = (part == 1 ? 1024 : 0) + sub * 64;
#pragma unroll
            for (int s = 0; s < 4; s++) {
                int row = r0 + s * 32;
                ra[s] = *(const uint4*)(Ag + (size_t)row * 2048 + ka + c8);
                rb[s] = *(const uint4*)(Bg + (size_t)row * 2048 + kb + c8);
            }
        }
        {
            const __nv_bfloat16* As = smb + (c & 1) * 2 * ABUF;
            const __nv_bfloat16* Bs = As + ABUF;
#pragma unroll
            for (int kk = 0; kk < 4; kk++) {
                const int k = kk * 16;
                wmma::fragment<wmma::matrix_a, 16, 16, 16, __nv_bfloat16, wmma::row_major> af[2];
                wmma::fragment<wmma::matrix_b, 16, 16, 16, __nv_bfloat16, wmma::col_major> bf[4];
                wmma::load_matrix_sync(af[0], As + (wm * 32 +  0) * SLD + k, SLD);
                wmma::load_matrix_sync(af[1], As + (wm * 32 + 16) * SLD + k, SLD);
#pragma unroll
                for (int j = 0; j < 4; j++)
                    wmma::load_matrix_sync(bf[j], Bs + (wn * 64 + j * 16) * SLD + k, SLD);
#pragma unroll
                for (int i = 0; i < 2; i++)
#pragma unroll
                    for (int j = 0; j < 4; j++)
                        wmma::mma_sync(acc[i][j], af[i], bf[j], acc[i][j]);
            }
        }
        if (c + 1 < GEMM_NCHUNK) {
            __nv_bfloat16* As = smb + ((c + 1) & 1) * 2 * ABUF;
            __nv_bfloat16* Bs = As + ABUF;
#pragma unroll
            for (int s = 0; s < 4; s++) {
                int row = r0 + s * 32;
                *(uint4*)(As + row * SLD + c8) = ra[s];
                *(uint4*)(Bs + row * SLD + c8) = rb[s];
            }
        }
        __syncthreads();
    }

#pragma unroll
    for (int i = 0; i < 2; i++)
#pragma unroll
        for (int j = 0; j < 4; j++)
            wmma::store_matrix_sync(
                C + (size_t)(m0 + wm * 32 + i * 16) * 1024 + n0 + wn * 64 + j * 16,
                acc[i][j], 1024, wmma::mem_row_major);
}

// ---------------- cosine-norm + scale + rotary + bf16 split (q,k) + v split -----
__global__ __launch_bounds__(512) void normrope_kernel(const float* __restrict__ s_qk)
{
    const int t    = blockIdx.x;
    const int h    = threadIdx.x >> 5;
    const int lane = threadIdx.x & 31;

    float c, s;
    if (lane < 16) {
        float theta = (float)t * FREQ16[lane];
        sincosf(theta, &s, &c);
    } else { c = 1.0f; s = 0.0f; }

    const float sc1 = s_qk[h * HD + lane]      * 32.0f;
    const float sc2 = s_qk[h * HD + lane + 32] * 32.0f;

    const size_t base = (size_t)t * DIM_ + h * HD;

    const float* inp[2] = {g_q + base, g_k + base};
    __nv_bfloat16* oh[2] = {g_qh + base, g_kh + base};
    __nv_bfloat16* ol[2] = {g_ql + base, g_kl + base};
#pragma unroll
    for (int w = 0; w < 2; w++) {
        const float* p = inp[w];
        float v1 = p[lane];
        float v2 = p[lane + 32];
        float ss = v1 * v1 + v2 * v2;
#pragma unroll
        for (int o = 16; o > 0; o >>= 1)
            ss += __shfl_xor_sync(0xffffffffu, ss, o);
        float rn = rsqrtf(ss + 1e-12f);
        v1 *= rn * sc1;
        v2 *= rn * sc2;
        float y1 = v1 * c + v2 * s;
        float y2 = v2 * c - v1 * s;
        __nv_bfloat16 h1 = __float2bfloat16(y1);
        __nv_bfloat16 h2 = __float2bfloat16(y2);
        oh[w][lane]      = h1;
        oh[w][lane + 32] = h2;
        ol[w][lane]      = __float2bfloat16(y1 - __bfloat162float(h1));
        ol[w][lane + 32] = __float2bfloat16(y2 - __bfloat162float(h2));
    }
    // v split (no norm/rope)
    {
        float v1 = g_v[base + lane];
        float v2 = g_v[base + lane + 32];
        __nv_bfloat16 h1 = __float2bfloat16(v1);
        __nv_bfloat16 h2 = __float2bfloat16(v2);
        g_vh[base + lane]      = h1;
        g_vh[base + lane + 32] = h2;
        g_vl[base + lane]      = __float2bfloat16(v1 - __bfloat162float(h1));
        g_vl[base + lane + 32] = __float2bfloat16(v2 - __bfloat162float(h2));
    }
}

// ---------------- WMMA split-bf16 flash attention --------------------------------
// grid (32 qb, 16 h), 256 threads (8 warps: 4m x 2n over 64x64 tiles).
// S = 3-term split QK^T (tensor), online softmax scalar, O += 3-term split P.V.
// P overlays the dead S buffer (register-staged). O in smem fp32, reloaded as
// accumulator fragments each tile. 92.7 KB smem -> 2 CTA/SM.
#define ALD 72
#define ATT_SMEM 92672

__global__ __launch_bounds__(256) void attn_wmma()
{
    extern __shared__ char smc[];
    __nv_bfloat16* Qh = (__nv_bfloat16*)(smc);
    __nv_bfloat16* Ql = (__nv_bfloat16*)(smc + 9216);
    __nv_bfloat16* Kh = (__nv_bfloat16*)(smc + 18432);
    __nv_bfloat16* Kl = (__nv_bfloat16*)(smc + 27648);
    __nv_bfloat16* Vh = (__nv_bfloat16*)(smc + 36864);
    __nv_bfloat16* Vl = (__nv_bfloat16*)(smc + 46080);
    float*         Ss = (float*)(smc + 55296);          // 64x72 fp32; dead after softmax
    __nv_bfloat16* Ph = (__nv_bfloat16*)(smc + 55296);  // overlays Ss
    __nv_bfloat16* Pl = (__nv_bfloat16*)(smc + 64512);
    float*         Os = (float*)(smc + 73728);          // 64x72 fp32
    float*         m_s = (float*)(smc + 92160);
    float*         l_s = (float*)(smc + 92416);

    const int qb  = 31 - (int)blockIdx.x;
    const int h   = blockIdx.y;
    const int tid = threadIdx.x;
    const int wid = tid >> 5;
    const int wm  = wid >> 1;          // 0..3 -> q rows wm*16
    const int wn  = wid & 1;           // 0..1 -> cols wn*32

    const int r2 = tid >> 3;           // tile-load row helper (slot layout)
    const int c8 = (tid & 7) * 8;

    // load Q tiles (hi/lo), 64 rows x 64 bf16
    {
        const __nv_bfloat16* Ghi = g_qh + (size_t)(qb * 64) * DIM_ + h * HD;
        const __nv_bfloat16* Glo = g_ql + (size_t)(qb * 64) * DIM_ + h * HD;
#pragma unroll
        for (int s = 0; s < 2; s++) {
            int slot = tid + s * 256;
            int r = slot >> 3, cc = (slot & 7) * 8;
            *(uint4*)(Qh + r * ALD + cc) = *(const uint4*)(Ghi + (size_t)r * DIM_ + cc);
            *(uint4*)(Ql + r * ALD + cc) = *(const uint4*)(Glo + (size_t)r * DIM_ + cc);
        }
    }
    // init O, m, l
    for (int p = tid; p < 64 * ALD; p += 256) Os[p] = 0.0f;
    if (tid < 64) { m_s[tid] = -1e30f; l_s[tid] = 0.0f; }

    const int row = tid >> 2;          // softmax: 4 threads per q row
    const int pp  = tid & 3;

    for (int kb = 0; kb <= qb; kb++) {
        __syncthreads();   // prev iter's PV done with K/V/P
        {
            const __nv_bfloat16* GKh = g_kh + (size_t)(kb * 64) * DIM_ + h * HD;
            const __nv_bfloat16* GKl = g_kl + (size_t)(kb * 64) * DIM_ + h * HD;
            const __nv_bfloat16* GVh = g_vh + (size_t)(kb * 64) * DIM_ + h * HD;
            const __nv_bfloat16* GVl = g_vl + (size_t)(kb * 64) * DIM_ + h * HD;
#pragma unroll
            for (int s = 0; s < 2; s++) {
                int slot = tid + s * 256;
                int r = slot >> 3, cc = (slot & 7) * 8;
                *(uint4*)(Kh + r * ALD + cc) = *(const uint4*)(GKh + (size_t)r * DIM_ + cc);
                *(uint4*)(Kl + r * ALD + cc) = *(const uint4*)(GKl + (size_t)r * DIM_ + cc);
                *(uint4*)(Vh + r * ALD + cc) = *(const uint4*)(GVh + (size_t)r * DIM_ + cc);
                *(uint4*)(Vl + r * ALD + cc) = *(const uint4*)(GVl + (size_t)r * DIM_ + cc);
            }
        }
        __syncthreads();

        // ---- S = QK^T (3-term split) ----
        {
            wmma::fragment<wmma::accumulator, 16, 16, 16, float> sfr[2];
            wmma::fill_fragment(sfr[0], 0.0f);
            wmma::fill_fragment(sfr[1], 0.0f);
#pragma unroll
            for (int sp = 0; sp < 3; sp++) {
                const __nv_bfloat16* Ap = (sp == 2) ? Ql : Qh;
                const __nv_bfloat16* Bp = (sp == 1) ? Kl : Kh;
#pragma unroll
                for (int ks = 0; ks < 4; ks++) {
                    wmma::fragment<wmma::matrix_a, 16, 16, 16, __nv_bfloat16, wmma::row_major> af;
                    wmma::fragment<wmma::matrix_b, 16, 16, 16, __nv_bfloat16, wmma::col_major> bf0, bf1;
                    wmma::load_matrix_sync(af,  Ap + (wm * 16) * ALD + ks * 16, ALD);
                    wmma::load_matrix_sync(bf0, Bp + (wn * 32) * ALD + ks * 16, ALD);
                    wmma::load_matrix_sync(bf1, Bp + (wn * 32 + 16) * ALD + ks * 16, ALD);
                    wmma::mma_sync(sfr[0], af, bf0, sfr[0]);
                    wmma::mma_sync(sfr[1], af, bf1, sfr[1]);
                }
            }
            wmma::store_matrix_sync(Ss + (wm * 16) * ALD + wn * 32,      sfr[0], ALD, wmma::mem_row_major);
            wmma::store_matrix_sync(Ss + (wm * 16) * ALD + wn * 32 + 16, sfr[1], ALD, wmma::mem_row_major);
        }
        __syncthreads();

        // ---- online softmax (scalar, 4 threads/row), O rescale, P = split(exp) ----
        {
            const bool diag = (kb == qb);
            float vreg[16];
            float mloc = -1e30f;
#pragma unroll
            for (int j = 0; j < 16; j++) {
                int cc = pp * 16 + j;
                float v = Ss[row * ALD + cc] * ATTN_SCALE;
                if (diag && cc > row) v = -1e30f;
                vreg[j] = v;
                mloc = fmaxf(mloc, v);
            }
            mloc = fmaxf(mloc, __shfl_xor_sync(0xffffffffu, mloc, 1));
            mloc = fmaxf(mloc, __shfl_xor_sync(0xffffffffu, mloc, 2));
            float mold = m_s[row];
            float mnew = fmaxf(mold, mloc);
            float sum = 0.0f;
#pragma unroll
            for (int j = 0; j < 16; j++) {
                float e = __expf(vreg[j] - mnew);
                vreg[j] = e;
                sum += e;
            }
            sum += __shfl_xor_sync(0xffffffffu, sum, 1);
            sum += __shfl_xor_sync(0xffffffffu, sum, 2);
            float corr = __expf(mold - mnew);
            if (pp == 0) {
                m_s[row] = mnew;
                l_s[row] = l_s[row] * corr + sum;
            }
#pragma unroll
            for (int j = 0; j < 16; j++)
                Os[row * ALD + pp * 16 + j] *= corr;
            __syncthreads();   // all reads of Ss done -> safe to overlay P
#pragma unroll
            for (int j = 0; j < 16; j++) {
                int cc = pp * 16 + j;
                __nv_bfloat16 hi = __float2bfloat16(vreg[j]);
                Ph[row * ALD + cc] = hi;
                Pl[row * ALD + cc] = __float2bfloat16(vreg[j] - __bfloat162float(hi));
            }
        }
        __syncthreads();

        // ---- O += P V (3-term split), O fragments from smem ----
        {
            wmma::fragment<wmma::accumulator, 16, 16, 16, float> ofr[2];
            wmma::load_matrix_sync(ofr[0], Os + (wm * 16) * ALD + wn * 32,      ALD, wmma::mem_row_major);
            wmma::load_matrix_sync(ofr[1], Os + (wm * 16) * ALD + wn * 32 + 16, ALD, wmma::mem_row_major);
#pragma unroll
            for (int sp = 0; sp < 3; sp++) {
                const __nv_bfloat16* Ap = (sp == 2) ? Pl : Ph;
                const __nv_bfloat16* Bp = (sp == 1) ? Vl : Vh;
#pragma unroll
                for (int ks = 0; ks < 4; ks++) {
                    wmma::fragment<wmma::matrix_a, 16, 16, 16, __nv_bfloat16, wmma::row_major> af;
                    wmma::fragment<wmma::matrix_b, 16, 16, 16, __nv_bfloat16, wmma::row_major> bf0, bf1;
                    wmma::load_matrix_sync(af,  Ap + (wm * 16) * ALD + ks * 16, ALD);
                    wmma::load_matrix_sync(bf0, Bp + (ks * 16) * ALD + wn * 32, ALD);
                    wmma::load_matrix_sync(bf1, Bp + (ks * 16) * ALD + wn * 32 + 16, ALD);
                    wmma::mma_sync(ofr[0], af, bf0, ofr[0]);
                    wmma::mma_sync(ofr[1], af, bf1, ofr[1]);
                }
            }
            wmma::store_matrix_sync(Os + (wm * 16) * ALD + wn * 32,      ofr[0], ALD, wmma::mem_row_major);
            wmma::store_matrix_sync(Os + (wm * 16) * ALD + wn * 32 + 16, ofr[1], ALD, wmma::mem_row_major);
        }
    }

    __syncthreads();
    // epilogue: y = O / l
    {
        float inv = 1.0f / l_s[row];
        float* Yg = g_y + (size_t)(qb * 64 + row) * DIM_ + h * HD;
#pragma unroll
        for (int j = 0; j < 16; j++)
            Yg[pp * 16 + j] = Os[row * ALD + pp * 16 + j] * inv;
    }
}

// ---------------- launcher ------------------------------------------------------
extern "C" void kernel_launch(void* const* d_in, const int* in_sizes, int n_in,
                              void* d_out, int out_size)
{
    const float* x    = (const float*)d_in[0];
    const float* Wq   = (const float*)d_in[1];
    const float* Wk   = (const float*)d_in[2];
    const float* Wv   = (const float*)d_in[3];
    const float* Wo   = (const float*)d_in[4];
    const float* s_qk = (const float*)d_in[5];
    float* out = (float*)d_out;

    cudaFuncSetAttribute(gemm_wmma, cudaFuncAttributeMaxDynamicSharedMemorySize,
                         GEMM_SMEM);
    cudaFuncSetAttribute(attn_wmma, cudaFuncAttributeMaxDynamicSharedMemorySize,
                         ATT_SMEM);

    // operand prep
    split_kernel<<<2048, 256>>>(x, 0);
    wconv_kernel<<<dim3(32, 32, 4), 256>>>(Wq, Wk, Wv, Wo);

    // QKV projections (split-bf16 WMMA, logical K'=3072)
    gemm_wmma<<<dim3(8, 16, 3), 256, GEMM_SMEM>>>(0, nullptr);

    // norm + rope + bf16 split for attention
    normrope_kernel<<<T_LEN, 512>>>(s_qk);

    // tensorized flash attention
    attn_wmma<<<dim3(32, NHEAD), 256, ATT_SMEM>>>();

    // output projection
    split_kernel<<<2048, 256>>>(nullptr, 1);
    gemm_wmma<<<dim3(8, 16, 1), 256, GEMM_SMEM>>>(1, out);
}

// round 8
// speedup vs baseline: 2.3965x; 1.2019x over previous
#include <cuda_runtime.h>
#include <cuda_bf16.h>
#include <mma.h>
#include <math.h>
#include <stdint.h>

using namespace nvcuda;

#define T_LEN 2048
#define DIM_  1024
#define NHEAD 16
#define HD    64
#define ATTN_SCALE 0.12f

// ---------------- scratch (static device memory; no allocations) ----------------
__device__ float g_q[T_LEN * DIM_];
__device__ float g_k[T_LEN * DIM_];
__device__ float g_v[T_LEN * DIM_];
__device__ float g_y[T_LEN * DIM_];
// split-bf16 operands for GEMMs: [.,0:1024)=hi, [.,1024:2048)=lo
__device__ __nv_bfloat16 g_abig[T_LEN * 2048];
__device__ __nv_bfloat16 g_ybig[T_LEN * 2048];
__device__ __nv_bfloat16 g_wt[4][1024 * 2048];
// split-bf16 q/k/v for attention (post norm+rope), layout [t][1024]
__device__ __nv_bfloat16 g_qh[T_LEN * DIM_], g_ql[T_LEN * DIM_];
__device__ __nv_bfloat16 g_kh[T_LEN * DIM_], g_kl[T_LEN * DIM_];
__device__ __nv_bfloat16 g_vh[T_LEN * DIM_], g_vl[T_LEN * DIM_];

// rotary freqs (fp32 of 2^(-2i/3), matches (1/1024)^(i/15) computed in double)
__constant__ float FREQ16[16] = {
    1.0f, 0.6299605249474366f, 0.3968502629920499f, 0.25f,
    0.15749013123685915f, 0.09921256574801247f, 0.0625f, 0.03937253280921479f,
    0.024803141437003118f, 0.015625f, 0.009843133202303698f, 0.0062007853592507794f,
    0.00390625f, 0.0024607833005759246f, 0.0015501963398126949f, 0.0009765625f
};

// ---------------- raw mma.sync helper -------------------------------------------
__device__ __forceinline__ void mma16816(float c[4],
                                         uint32_t a0, uint32_t a1, uint32_t a2, uint32_t a3,
                                         uint32_t b0, uint32_t b1)
{
    asm volatile("mma.sync.aligned.m16n8k16.row.col.f32.bf16.bf16.f32 "
                 "{%0,%1,%2,%3}, {%4,%5,%6,%7}, {%8,%9}, {%0,%1,%2,%3};"
                 : "+f"(c[0]), "+f"(c[1]), "+f"(c[2]), "+f"(c[3])
                 : "r"(a0), "r"(a1), "r"(a2), "r"(a3), "r"(b0), "r"(b1));
}
__device__ __forceinline__ uint32_t pack_bf16(__nv_bfloat16 lo, __nv_bfloat16 hi)
{
    __nv_bfloat162 t; t.x = lo; t.y = hi;
    return *(uint32_t*)&t;
}

// ---------------- split conversion (x or y -> hi|lo bf16) -----------------------
__global__ __launch_bounds__(256) void split_kernel(const float* __restrict__ xin, int which)
{
    const float* in = which ? g_y : xin;
    __nv_bfloat16* outp = which ? g_ybig : g_abig;
    int idx = blockIdx.x * 256 + threadIdx.x;
    float4 v = ((const float4*)in)[idx];
    int m  = idx >> 8;
    int c0 = (idx & 255) << 2;
    __nv_bfloat16 h0 = __float2bfloat16(v.x), h1 = __float2bfloat16(v.y);
    __nv_bfloat16 h2 = __float2bfloat16(v.z), h3 = __float2bfloat16(v.w);
    __nv_bfloat16 l0 = __float2bfloat16(v.x - __bfloat162float(h0));
    __nv_bfloat16 l1 = __float2bfloat16(v.y - __bfloat162float(h1));
    __nv_bfloat16 l2 = __float2bfloat16(v.z - __bfloat162float(h2));
    __nv_bfloat16 l3 = __float2bfloat16(v.w - __bfloat162float(h3));
    __nv_bfloat16* po = outp + (size_t)m * 2048 + c0;
    po[0] = h0; po[1] = h1; po[2] = h2; po[3] = h3;
    po[1024] = l0; po[1025] = l1; po[1026] = l2; po[1027] = l3;
}

// ---------------- weight transpose + split: W[k][n] -> WT[n][k_hi | k_lo] -------
__global__ __launch_bounds__(256) void wconv_kernel(const float* __restrict__ Wq,
                                                    const float* __restrict__ Wk,
                                                    const float* __restrict__ Wv,
                                                    const float* __restrict__ Wo)
{
    __shared__ float tile[32][33];
    const int z = blockIdx.z;
    const float* W = (z == 0) ? Wq : (z == 1) ? Wk : (z == 2) ? Wv : Wo;
    __nv_bfloat16* WT = g_wt[z];
    const int tx = threadIdx.x & 31, ty = threadIdx.x >> 5;
    const int n  = blockIdx.x * 32 + tx;
    const int k0 = blockIdx.y * 32;
#pragma unroll
    for (int i = 0; i < 4; i++)
        tile[ty + i * 8][tx] = W[(size_t)(k0 + ty + i * 8) * 1024 + n];
    __syncthreads();
#pragma unroll
    for (int i = 0; i < 4; i++) {
        float v = tile[tx][ty + i * 8];
        __nv_bfloat16 hi = __float2bfloat16(v);
        __nv_bfloat16 lo = __float2bfloat16(v - __bfloat162float(hi));
        size_t base = (size_t)(blockIdx.x * 32 + ty + i * 8) * 2048 + k0 + tx;
        WT[base]        = hi;
        WT[base + 1024] = lo;
    }
}

// ---------------- WMMA split-bf16 GEMM (unchanged, passing) ---------------------
#define GEMM_NCHUNK 48
#define SLD 72
#define ABUF (128 * SLD)
#define GEMM_SMEM (2 * 2 * ABUF * 2)

__global__ __launch_bounds__(256) void gemm_wmma(int proj, float* __restrict__ outp)
{
    extern __shared__ __nv_bfloat16 smb[];
    const int tid = threadIdx.x;
    const int wid = tid >> 5;
    const int n0 = blockIdx.x * 128;
    const int m0 = blockIdx.y * 128;
    const int z  = blockIdx.z;

    const __nv_bfloat16* A  = proj ? g_ybig : g_abig;
    const __nv_bfloat16* Bt = proj ? g_wt[3] : g_wt[z];
    float* C = proj ? outp : (z == 0 ? g_q : z == 1 ? g_k : g_v);

    const __nv_bfloat16* Ag = A  + (size_t)m0 * 2048;
    const __nv_bfloat16* Bg = Bt + (size_t)n0 * 2048;

    const int wm = wid >> 1;
    const int wn = wid & 1;

    wmma::fragment<wmma::accumulator, 16, 16, 16, float> acc[2][4];
#pragma unroll
    for (int i = 0; i < 2; i++)
#pragma unroll
        for (int j = 0; j < 4; j++) wmma::fill_fragment(acc[i][j], 0.0f);

    const int r0 = tid >> 3;
    const int c8 = (tid & 7) * 8;

    uint4 ra[4], rb[4];
#pragma unroll
    for (int s = 0; s < 4; s++) {
        int row = r0 + s * 32;
        ra[s] = *(const uint4*)(Ag + (size_t)row * 2048 + c8);
        rb[s] = *(const uint4*)(Bg + (size_t)row * 2048 + c8);
    }
    {
        __nv_bfloat16* As = smb;
        __nv_bfloat16* Bs = smb + ABUF;
#pragma unroll
        for (int s = 0; s < 4; s++) {
            int row = r0 + s * 32;
            *(uint4*)(As + row * SLD + c8) = ra[s];
            *(uint4*)(Bs + row * SLD + c8) = rb[s];
        }
    }
    __syncthreads();

    for (int c = 0; c < GEMM_NCHUNK; c++) {
        if (c + 1 < GEMM_NCHUNK) {
            const int cn = c + 1;
            const int part = cn >> 4, sub = cn & 15;
            const int ka = (part == 2 ? 1024 : 0) + sub * 64;
            const int kb = (part == 1 ? 1024 : 0) + sub * 64;
#pragma unroll
            for (int s = 0; s < 4; s++) {
                int row = r0 + s * 32;
                ra[s] = *(const uint4*)(Ag + (size_t)row * 2048 + ka + c8);
                rb[s] = *(const uint4*)(Bg + (size_t)row * 2048 + kb + c8);
            }
        }
        {
            const __nv_bfloat16* As = smb + (c & 1) * 2 * ABUF;
            const __nv_bfloat16* Bs = As + ABUF;
#pragma unroll
            for (int kk = 0; kk < 4; kk++) {
                const int k = kk * 16;
                wmma::fragment<wmma::matrix_a, 16, 16, 16, __nv_bfloat16, wmma::row_major> af[2];
                wmma::fragment<wmma::matrix_b, 16, 16, 16, __nv_bfloat16, wmma::col_major> bf[4];
                wmma::load_matrix_sync(af[0], As + (wm * 32 +  0) * SLD + k, SLD);
                wmma::load_matrix_sync(af[1], As + (wm * 32 + 16) * SLD + k, SLD);
#pragma unroll
                for (int j = 0; j < 4; j++)
                    wmma::load_matrix_sync(bf[j], Bs + (wn * 64 + j * 16) * SLD + k, SLD);
#pragma unroll
                for (int i = 0; i < 2; i++)
#pragma unroll
                    for (int j = 0; j < 4; j++)
                        wmma::mma_sync(acc[i][j], af[i], bf[j], acc[i][j]);
            }
        }
        if (c + 1 < GEMM_NCHUNK) {
            __nv_bfloat16* As = smb + ((c + 1) & 1) * 2 * ABUF;
            __nv_bfloat16* Bs = As + ABUF;
#pragma unroll
            for (int s = 0; s < 4; s++) {
                int row = r0 + s * 32;
                *(uint4*)(As + row * SLD + c8) = ra[s];
                *(uint4*)(Bs + row * SLD + c8) = rb[s];
            }
        }
        __syncthreads();
    }

#pragma unroll
    for (int i = 0; i < 2; i++)
#pragma unroll
        for (int j = 0; j < 4; j++)
            wmma::store_matrix_sync(
                C + (size_t)(m0 + wm * 32 + i * 16) * 1024 + n0 + wn * 64 + j * 16,
                acc[i][j], 1024, wmma::mem_row_major);
}

// ---------------- cosine-norm + scale + rotary + bf16 split ---------------------
__global__ __launch_bounds__(512) void normrope_kernel(const float* __restrict__ s_qk)
{
    const int t    = blockIdx.x;
    const int h    = threadIdx.x >> 5;
    const int lane = threadIdx.x & 31;

    float c, s;
    if (lane < 16) {
        float theta = (float)t * FREQ16[lane];
        sincosf(theta, &s, &c);
    } else { c = 1.0f; s = 0.0f; }

    const float sc1 = s_qk[h * HD + lane]      * 32.0f;
    const float sc2 = s_qk[h * HD + lane + 32] * 32.0f;

    const size_t base = (size_t)t * DIM_ + h * HD;

    const float* inp[2] = {g_q + base, g_k + base};
    __nv_bfloat16* oh[2] = {g_qh + base, g_kh + base};
    __nv_bfloat16* ol[2] = {g_ql + base, g_kl + base};
#pragma unroll
    for (int w = 0; w < 2; w++) {
        const float* p = inp[w];
        float v1 = p[lane];
        float v2 = p[lane + 32];
        float ss = v1 * v1 + v2 * v2;
#pragma unroll
        for (int o = 16; o > 0; o >>= 1)
            ss += __shfl_xor_sync(0xffffffffu, ss, o);
        float rn = rsqrtf(ss + 1e-12f);
        v1 *= rn * sc1;
        v2 *= rn * sc2;
        float y1 = v1 * c + v2 * s;
        float y2 = v2 * c - v1 * s;
        __nv_bfloat16 h1 = __float2bfloat16(y1);
        __nv_bfloat16 h2 = __float2bfloat16(y2);
        oh[w][lane]      = h1;
        oh[w][lane + 32] = h2;
        ol[w][lane]      = __float2bfloat16(y1 - __bfloat162float(h1));
        ol[w][lane + 32] = __float2bfloat16(y2 - __bfloat162float(h2));
    }
    {
        float v1 = g_v[base + lane];
        float v2 = g_v[base + lane + 32];
        __nv_bfloat16 h1 = __float2bfloat16(v1);
        __nv_bfloat16 h2 = __float2bfloat16(v2);
        g_vh[base + lane]      = h1;
        g_vh[base + lane + 32] = h2;
        g_vl[base + lane]      = __float2bfloat16(v1 - __bfloat162float(h1));
        g_vl[base + lane + 32] = __float2bfloat16(v2 - __bfloat162float(h2));
    }
}

// ---------------- register-resident flash attention (raw mma.sync) --------------
// grid (32 qb, 16 h), 128 threads = 4 warps. Warp w owns q rows w*16..w*16+15
// and ALL 64 keys of each tile: softmax entirely in-warp, O in registers.
// smem: K row-major + V transposed, hi/lo split. 3-term split everywhere.
#define ALD 72
#define ATT_SMEM (4 * 64 * ALD * 2)     // Kh,Kl,VTh,VTl bf16 = 36864 B

__global__ __launch_bounds__(128) void attn_mma()
{
    extern __shared__ __nv_bfloat16 smx[];
    __nv_bfloat16* Kh  = smx;
    __nv_bfloat16* Kl  = smx + 64 * ALD;
    __nv_bfloat16* VTh = smx + 2 * 64 * ALD;   // [hd][key]
    __nv_bfloat16* VTl = smx + 3 * 64 * ALD;

    const int qb   = 31 - (int)blockIdx.x;     // heavy blocks first
    const int h    = blockIdx.y;
    const int tid  = threadIdx.x;
    const int wid  = tid >> 5;
    const int lane = tid & 31;
    const int lr   = lane >> 2;                // 0..7
    const int lc   = lane & 3;                 // 0..3

    // ---- hoist Q A-fragments (hi/lo) straight from global ----
    const size_t qrow0 = (size_t)(qb * 64 + wid * 16 + lr) * DIM_ + h * HD;
    const size_t qrow8 = qrow0 + 8 * DIM_;
    uint32_t qa_h[4][4], qa_l[4][4];
#pragma unroll
    for (int t = 0; t < 4; t++) {
        const int c0 = t * 16 + 2 * lc;
        qa_h[t][0] = *(const uint32_t*)(g_qh + qrow0 + c0);
        qa_h[t][1] = *(const uint32_t*)(g_qh + qrow8 + c0);
        qa_h[t][2] = *(const uint32_t*)(g_qh + qrow0 + c0 + 8);
        qa_h[t][3] = *(const uint32_t*)(g_qh + qrow8 + c0 + 8);
        qa_l[t][0] = *(const uint32_t*)(g_ql + qrow0 + c0);
        qa_l[t][1] = *(const uint32_t*)(g_ql + qrow8 + c0);
        qa_l[t][2] = *(const uint32_t*)(g_ql + qrow0 + c0 + 8);
        qa_l[t][3] = *(const uint32_t*)(g_ql + qrow8 + c0 + 8);
    }

    float ofr[8][4];
#pragma unroll
    for (int j = 0; j < 8; j++)
#pragma unroll
        for (int q = 0; q < 4; q++) ofr[j][q] = 0.0f;
    float m0 = -1e30f, m1 = -1e30f, l0 = 0.0f, l1 = 0.0f;

    const int gr0 = qb * 64 + wid * 16 + lr;   // global q rows of this lane
    const int gr8 = gr0 + 8;

    for (int kb = 0; kb <= qb; kb++) {
        __syncthreads();   // previous iteration done reading K/VT smem
        // ---- load K tiles (row-major) ----
        {
            const __nv_bfloat16* GKh = g_kh + (size_t)(kb * 64) * DIM_ + h * HD;
            const __nv_bfloat16* GKl = g_kl + (size_t)(kb * 64) * DIM_ + h * HD;
            const int r  = tid >> 1;
            const int cc = (tid & 1) * 32;
#pragma unroll
            for (int s = 0; s < 4; s++) {
                *(uint4*)(Kh + r * ALD + cc + s * 8) =
                    *(const uint4*)(GKh + (size_t)r * DIM_ + cc + s * 8);
                *(uint4*)(Kl + r * ALD + cc + s * 8) =
                    *(const uint4*)(GKl + (size_t)r * DIM_ + cc + s * 8);
            }
        }
        // ---- load V transposed: VT[hd][key], paired-key b32 stores ----
        {
            const __nv_bfloat16* GVh = g_vh + (size_t)(kb * 64) * DIM_ + h * HD;
            const __nv_bfloat16* GVl = g_vl + (size_t)(kb * 64) * DIM_ + h * HD;
            const int k0 = (tid >> 2) * 2;         // key pair base
#pragma unroll
            for (int s = 0; s < 2; s++) {
                const int hb = (tid & 3) * 8 + s * 32;
                uint4 va = *(const uint4*)(GVh + (size_t)k0 * DIM_ + hb);
                uint4 vb = *(const uint4*)(GVh + (size_t)(k0 + 1) * DIM_ + hb);
                const ushort* pa = (const ushort*)&va;
                const ushort* pb = (const ushort*)&vb;
#pragma unroll
                for (int j = 0; j < 8; j++)
                    *(uint32_t*)(VTh + (hb + j) * ALD + k0) =
                        (uint32_t)pa[j] | ((uint32_t)pb[j] << 16);
                uint4 wa = *(const uint4*)(GVl + (size_t)k0 * DIM_ + hb);
                uint4 wb = *(const uint4*)(GVl + (size_t)(k0 + 1) * DIM_ + hb);
                const ushort* qa = (const ushort*)&wa;
                const ushort* qv = (const ushort*)&wb;
#pragma unroll
                for (int j = 0; j < 8; j++)
                    *(uint32_t*)(VTl + (hb + j) * ALD + k0) =
                        (uint32_t)qa[j] | ((uint32_t)qv[j] << 16);
            }
        }
        __syncthreads();

        // ---- S = Q K^T (3-term split), accumulators in registers ----
        float sfr[8][4];
#pragma unroll
        for (int j = 0; j < 8; j++)
#pragma unroll
            for (int q = 0; q < 4; q++) sfr[j][q] = 0.0f;

#pragma unroll
        for (int t = 0; t < 4; t++) {
#pragma unroll
            for (int j = 0; j < 8; j++) {
                const int boff = (j * 8 + lr) * ALD + t * 16 + 2 * lc;
                uint32_t bh0 = *(const uint32_t*)(Kh + boff);
                uint32_t bh1 = *(const uint32_t*)(Kh + boff + 8);
                uint32_t bl0 = *(const uint32_t*)(Kl + boff);
                uint32_t bl1 = *(const uint32_t*)(Kl + boff + 8);
                mma16816(sfr[j], qa_h[t][0], qa_h[t][1], qa_h[t][2], qa_h[t][3], bh0, bh1);
                mma16816(sfr[j], qa_h[t][0], qa_h[t][1], qa_h[t][2], qa_h[t][3], bl0, bl1);
                mma16816(sfr[j], qa_l[t][0], qa_l[t][1], qa_l[t][2], qa_l[t][3], bh0, bh1);
            }
        }

        // ---- scale + causal mask (registers) ----
        const bool diag = (kb == qb);
#pragma unroll
        for (int j = 0; j < 8; j++) {
            const int gc = kb * 64 + j * 8 + 2 * lc;
            float v0 = sfr[j][0] * ATTN_SCALE;
            float v1 = sfr[j][1] * ATTN_SCALE;
            float v2 = sfr[j][2] * ATTN_SCALE;
            float v3 = sfr[j][3] * ATTN_SCALE;
            if (diag) {
                if (gc     > gr0) v0 = -1e30f;
                if (gc + 1 > gr0) v1 = -1e30f;
                if (gc     > gr8) v2 = -1e30f;
                if (gc + 1 > gr8) v3 = -1e30f;
            }
            sfr[j][0] = v0; sfr[j][1] = v1; sfr[j][2] = v2; sfr[j][3] = v3;
        }

        // ---- in-warp online softmax ----
        float mx0 = -1e30f, mx1 = -1e30f;
#pragma unroll
        for (int j = 0; j < 8; j++) {
            mx0 = fmaxf(mx0, fmaxf(sfr[j][0], sfr[j][1]));
            mx1 = fmaxf(mx1, fmaxf(sfr[j][2], sfr[j][3]));
        }
        mx0 = fmaxf(mx0, __shfl_xor_sync(0xffffffffu, mx0, 1));
        mx0 = fmaxf(mx0, __shfl_xor_sync(0xffffffffu, mx0, 2));
        mx1 = fmaxf(mx1, __shfl_xor_sync(0xffffffffu, mx1, 1));
        mx1 = fmaxf(mx1, __shfl_xor_sync(0xffffffffu, mx1, 2));
        const float mn0 = fmaxf(m0, mx0);
        const float mn1 = fmaxf(m1, mx1);
        const float cor0 = __expf(m0 - mn0);
        const float cor1 = __expf(m1 - mn1);
        m0 = mn0; m1 = mn1;
        float s0 = 0.0f, s1 = 0.0f;
#pragma unroll
        for (int j = 0; j < 8; j++) {
            sfr[j][0] = __expf(sfr[j][0] - mn0);
            sfr[j][1] = __expf(sfr[j][1] - mn0);
            sfr[j][2] = __expf(sfr[j][2] - mn1);
            sfr[j][3] = __expf(sfr[j][3] - mn1);
            s0 += sfr[j][0] + sfr[j][1];
            s1 += sfr[j][2] + sfr[j][3];
        }
        s0 += __shfl_xor_sync(0xffffffffu, s0, 1);
        s0 += __shfl_xor_sync(0xffffffffu, s0, 2);
        s1 += __shfl_xor_sync(0xffffffffu, s1, 1);
        s1 += __shfl_xor_sync(0xffffffffu, s1, 2);
        l0 = l0 * cor0 + s0;
        l1 = l1 * cor1 + s1;

        // ---- rescale O in registers ----
#pragma unroll
        for (int j = 0; j < 8; j++) {
            ofr[j][0] *= cor0; ofr[j][1] *= cor0;
            ofr[j][2] *= cor1; ofr[j][3] *= cor1;
        }

        // ---- O += P V (3-term split); P A-frags built from S C-frags ----
#pragma unroll
        for (int u = 0; u < 4; u++) {
            // split P into hi + residual, packed as bf16x2 A fragments
            __nv_bfloat16 b00 = __float2bfloat16(sfr[2*u][0]);
            __nv_bfloat16 b01 = __float2bfloat16(sfr[2*u][1]);
            __nv_bfloat16 b02 = __float2bfloat16(sfr[2*u][2]);
            __nv_bfloat16 b03 = __float2bfloat16(sfr[2*u][3]);
            __nv_bfloat16 b10 = __float2bfloat16(sfr[2*u+1][0]);
            __nv_bfloat16 b11 = __float2bfloat16(sfr[2*u+1][1]);
            __nv_bfloat16 b12 = __float2bfloat16(sfr[2*u+1][2]);
            __nv_bfloat16 b13 = __float2bfloat16(sfr[2*u+1][3]);
            uint32_t pah0 = pack_bf16(b00, b01);
            uint32_t pah1 = pack_bf16(b02, b03);
            uint32_t pah2 = pack_bf16(b10, b11);
            uint32_t pah3 = pack_bf16(b12, b13);
            uint32_t pal0 = pack_bf16(__float2bfloat16(sfr[2*u][0]   - __bfloat162float(b00)),
                                      __float2bfloat16(sfr[2*u][1]   - __bfloat162float(b01)));
            uint32_t pal1 = pack_bf16(__float2bfloat16(sfr[2*u][2]   - __bfloat162float(b02)),
                                      __float2bfloat16(sfr[2*u][3]   - __bfloat162float(b03)));
            uint32_t pal2 = pack_bf16(__float2bfloat16(sfr[2*u+1][0] - __bfloat162float(b10)),
                                      __float2bfloat16(sfr[2*u+1][1] - __bfloat162float(b11)));
            uint32_t pal3 = pack_bf16(__float2bfloat16(sfr[2*u+1][2] - __bfloat162float(b12)),
                                      __float2bfloat16(sfr[2*u+1][3] - __bfloat162float(b13)));
#pragma unroll
            for (int j2 = 0; j2 < 8; j2++) {
                const int boff = (j2 * 8 + lr) * ALD + u * 16 + 2 * lc;
                uint32_t bh0 = *(const uint32_t*)(VTh + boff);
                uint32_t bh1 = *(const uint32_t*)(VTh + boff + 8);
                uint32_t bl0 = *(const uint32_t*)(VTl + boff);
                uint32_t bl1 = *(const uint32_t*)(VTl + boff + 8);
                mma16816(ofr[j2], pah0, pah1, pah2, pah3, bh0, bh1);
                mma16816(ofr[j2], pah0, pah1, pah2, pah3, bl0, bl1);
                mma16816(ofr[j2], pal0, pal1, pal2, pal3, bh0, bh1);
            }
        }
    }

    // ---- epilogue: y = O / l ----
    const float inv0 = 1.0f / l0;
    const float inv1 = 1.0f / l1;
    float* Y0 = g_y + (size_t)gr0 * DIM_ + h * HD;
    float* Y8 = g_y + (size_t)gr8 * DIM_ + h * HD;
#pragma unroll
    for (int j2 = 0; j2 < 8; j2++) {
        const int cc = j2 * 8 + 2 * lc;
        *(float2*)(Y0 + cc) = make_float2(ofr[j2][0] * inv0, ofr[j2][1] * inv0);
        *(float2*)(Y8 + cc) = make_float2(ofr[j2][2] * inv1, ofr[j2][3] * inv1);
    }
}

// ---------------- launcher ------------------------------------------------------
extern "C" void kernel_launch(void* const* d_in, const int* in_sizes, int n_in,
                              void* d_out, int out_size)
{
    const float* x    = (const float*)d_in[0];
    const float* Wq   = (const float*)d_in[1];
    const float* Wk   = (const float*)d_in[2];
    const float* Wv   = (const float*)d_in[3];
    const float* Wo   = (const float*)d_in[4];
    const float* s_qk = (const float*)d_in[5];
    float* out = (float*)d_out;

    cudaFuncSetAttribute(gemm_wmma, cudaFuncAttributeMaxDynamicSharedMemorySize,
                         GEMM_SMEM);

    // operand prep
    split_kernel<<<2048, 256>>>(x, 0);
    wconv_kernel<<<dim3(32, 32, 4), 256>>>(Wq, Wk, Wv, Wo);

    // QKV projections (split-bf16 WMMA, logical K'=3072)
    gemm_wmma<<<dim3(8, 16, 3), 256, GEMM_SMEM>>>(0, nullptr);

    // norm + rope + bf16 split for attention
    normrope_kernel<<<T_LEN, 512>>>(s_qk);

    // register-resident flash attention
    attn_mma<<<dim3(32, NHEAD), 128, ATT_SMEM>>>();

    // output projection
    split_kernel<<<2048, 256>>>(nullptr, 1);
    gemm_wmma<<<dim3(8, 16, 1), 256, GEMM_SMEM>>>(1, out);
}

// round 9
// speedup vs baseline: 2.9690x; 1.2389x over previous
#include <cuda_runtime.h>
#include <cuda_bf16.h>
#include <math.h>
#include <stdint.h>

#define T_LEN 2048
#define DIM_  1024
#define NHEAD 16
#define HD    64
#define ATTN_SCALE 0.12f

// ---------------- scratch (static device memory; no allocations) ----------------
__device__ float g_q[T_LEN * DIM_];
__device__ float g_k[T_LEN * DIM_];
__device__ float g_v[T_LEN * DIM_];
__device__ float g_y[T_LEN * DIM_];
// split-bf16 operands for GEMMs: [.,0:1024)=hi, [.,1024:2048)=lo
__device__ __nv_bfloat16 g_abig[T_LEN * 2048];
__device__ __nv_bfloat16 g_ybig[T_LEN * 2048];
__device__ __nv_bfloat16 g_wt[4][1024 * 2048];
// split-bf16 q/k/v for attention (post norm+rope), layout [t][1024]
__device__ __nv_bfloat16 g_qh[T_LEN * DIM_], g_ql[T_LEN * DIM_];
__device__ __nv_bfloat16 g_kh[T_LEN * DIM_], g_kl[T_LEN * DIM_];
__device__ __nv_bfloat16 g_vh[T_LEN * DIM_], g_vl[T_LEN * DIM_];

// rotary freqs (fp32 of 2^(-2i/3), matches (1/1024)^(i/15) computed in double)
__constant__ float FREQ16[16] = {
    1.0f, 0.6299605249474366f, 0.3968502629920499f, 0.25f,
    0.15749013123685915f, 0.09921256574801247f, 0.0625f, 0.03937253280921479f,
    0.024803141437003118f, 0.015625f, 0.009843133202303698f, 0.0062007853592507794f,
    0.00390625f, 0.0024607833005759246f, 0.0015501963398126949f, 0.0009765625f
};

// ---------------- PTX helpers ----------------------------------------------------
__device__ __forceinline__ uint32_t smem_u32(const void* p) {
    uint32_t a;
    asm("{ .reg .u64 t; cvta.to.shared.u64 t, %1; cvt.u32.u64 %0, t; }" : "=r"(a) : "l"(p));
    return a;
}
__device__ __forceinline__ void mma16816(float c[4],
                                         uint32_t a0, uint32_t a1, uint32_t a2, uint32_t a3,
                                         uint32_t b0, uint32_t b1)
{
    asm volatile("mma.sync.aligned.m16n8k16.row.col.f32.bf16.bf16.f32 "
                 "{%0,%1,%2,%3}, {%4,%5,%6,%7}, {%8,%9}, {%0,%1,%2,%3};"
                 : "+f"(c[0]), "+f"(c[1]), "+f"(c[2]), "+f"(c[3])
                 : "r"(a0), "r"(a1), "r"(a2), "r"(a3), "r"(b0), "r"(b1));
}
__device__ __forceinline__ void ldm_x4(uint32_t r[4], uint32_t addr) {
    asm volatile("ldmatrix.sync.aligned.m8n8.x4.shared.b16 {%0,%1,%2,%3}, [%4];"
                 : "=r"(r[0]), "=r"(r[1]), "=r"(r[2]), "=r"(r[3]) : "r"(addr));
}
__device__ __forceinline__ uint32_t pack_bf16(__nv_bfloat16 lo, __nv_bfloat16 hi)
{
    __nv_bfloat162 t; t.x = lo; t.y = hi;
    return *(uint32_t*)&t;
}
#define CP_ASYNC16(dst, src) \
    asm volatile("cp.async.cg.shared.global [%0], [%1], 16;" :: "r"(dst), "l"(src))
#define CP_COMMIT()  asm volatile("cp.async.commit_group;" ::: "memory")
#define CP_WAIT1()   asm volatile("cp.async.wait_group 1;" ::: "memory")
#define CP_WAIT0()   asm volatile("cp.async.wait_group 0;" ::: "memory")
#define SWZ128(o)    ((o) ^ (((o) >> 3) & 0x70))

// ---------------- split conversion (x or y -> hi|lo bf16) -----------------------
__global__ __launch_bounds__(256) void split_kernel(const float* __restrict__ xin, int which)
{
    const float* in = which ? g_y : xin;
    __nv_bfloat16* outp = which ? g_ybig : g_abig;
    int idx = blockIdx.x * 256 + threadIdx.x;
    float4 v = ((const float4*)in)[idx];
    int m  = idx >> 8;
    int c0 = (idx & 255) << 2;
    __nv_bfloat16 h0 = __float2bfloat16(v.x), h1 = __float2bfloat16(v.y);
    __nv_bfloat16 h2 = __float2bfloat16(v.z), h3 = __float2bfloat16(v.w);
    __nv_bfloat16 l0 = __float2bfloat16(v.x - __bfloat162float(h0));
    __nv_bfloat16 l1 = __float2bfloat16(v.y - __bfloat162float(h1));
    __nv_bfloat16 l2 = __float2bfloat16(v.z - __bfloat162float(h2));
    __nv_bfloat16 l3 = __float2bfloat16(v.w - __bfloat162float(h3));
    __nv_bfloat16* po = outp + (size_t)m * 2048 + c0;
    po[0] = h0; po[1] = h1; po[2] = h2; po[3] = h3;
    po[1024] = l0; po[1025] = l1; po[1026] = l2; po[1027] = l3;
}

// ---------------- weight transpose + split: W[k][n] -> WT[n][k_hi | k_lo] -------
__global__ __launch_bounds__(256) void wconv_kernel(const float* __restrict__ Wq,
                                                    const float* __restrict__ Wk,
                                                    const float* __restrict__ Wv,
                                                    const float* __restrict__ Wo)
{
    __shared__ float tile[32][33];
    const int z = blockIdx.z;
    const float* W = (z == 0) ? Wq : (z == 1) ? Wk : (z == 2) ? Wv : Wo;
    __nv_bfloat16* WT = g_wt[z];
    const int tx = threadIdx.x & 31, ty = threadIdx.x >> 5;
    const int n  = blockIdx.x * 32 + tx;
    const int k0 = blockIdx.y * 32;
#pragma unroll
    for (int i = 0; i < 4; i++)
        tile[ty + i * 8][tx] = W[(size_t)(k0 + ty + i * 8) * 1024 + n];
    __syncthreads();
#pragma unroll
    for (int i = 0; i < 4; i++) {
        float v = tile[tx][ty + i * 8];
        __nv_bfloat16 hi = __float2bfloat16(v);
        __nv_bfloat16 lo = __float2bfloat16(v - __bfloat162float(hi));
        size_t base = (size_t)(blockIdx.x * 32 + ty + i * 8) * 2048 + k0 + tx;
        WT[base]        = hi;
        WT[base + 1024] = lo;
    }
}

// ---------------- raw-mma split-bf16 GEMM: C[2048,1024] = A' @ W'^T -------------
// 128x128 CTA tile, 256 thr, warp tile 32x64 (4m x 2n). 48 chunks of K=64 over
// the 3-term hi/lo schedule. 3-stage cp.async pipeline, SW128 swizzle, ldmatrix.
#define GEMM_NCHUNK 48
#define GSTAGES 3
#define STAGE_BYTES 32768                       // A 16KB + B 16KB
#define GEMM_SMEM (GSTAGES * STAGE_BYTES)       // 98304

__global__ __launch_bounds__(256, 2) void gemm_mma(int proj, float* __restrict__ outp)
{
    extern __shared__ char smg[];
    const uint32_t sbase = smem_u32(smg);
    const int tid  = threadIdx.x;
    const int wid  = tid >> 5;
    const int lane = tid & 31;
    const int n0 = blockIdx.x * 128;
    const int m0 = blockIdx.y * 128;
    const int z  = blockIdx.z;

    const __nv_bfloat16* A  = proj ? g_ybig : g_abig;
    const __nv_bfloat16* Bt = proj ? g_wt[3] : g_wt[z];
    float* C = proj ? outp : (z == 0 ? g_q : z == 1 ? g_k : g_v);

    const __nv_bfloat16* Ag = A  + (size_t)m0 * 2048;
    const __nv_bfloat16* Bg = Bt + (size_t)n0 * 2048;

    const int wm = wid >> 1;          // 0..3 -> m offset wm*32
    const int wn = wid & 1;           // 0..1 -> n offset wn*64
    const int quad = lane >> 3;       // ldmatrix address quad
    const int r8   = lane & 7;

    float acc[2][8][4];
#pragma unroll
    for (int i = 0; i < 2; i++)
#pragma unroll
        for (int f = 0; f < 8; f++)
#pragma unroll
            for (int q = 0; q < 4; q++) acc[i][f][q] = 0.0f;

    // ---- async chunk loader: 2048 16B granules (A 1024 + B 1024) ----
    auto load_chunk = [&](int cn) {
        const int part = cn >> 4, sub = cn & 15;
        const int ka = (part == 2 ? 1024 : 0) + sub * 64;   // A: hi,hi,lo
        const int kb = (part == 1 ? 1024 : 0) + sub * 64;   // B: hi,lo,hi
        const uint32_t As = sbase + (cn % GSTAGES) * STAGE_BYTES;
        const uint32_t Bs = As + 16384;
#pragma unroll
        for (int s = 0; s < 4; s++) {
            const int idx = tid + s * 256;
            const int row = idx >> 3, g = idx & 7;
            const uint32_t off = SWZ128((uint32_t)(row * 128 + g * 16));
            CP_ASYNC16(As + off, (const void*)(Ag + (size_t)row * 2048 + ka + g * 8));
            CP_ASYNC16(Bs + off, (const void*)(Bg + (size_t)row * 2048 + kb + g * 8));
        }
        CP_COMMIT();
    };

    load_chunk(0);
    load_chunk(1);

    for (int c = 0; c < GEMM_NCHUNK; c++) {
        if (c == GEMM_NCHUNK - 1) CP_WAIT0(); else CP_WAIT1();
        __syncthreads();                    // chunk c visible; all warps past stage (c-1)%3
        if (c + 2 < GEMM_NCHUNK) load_chunk(c + 2);   // writes stage (c+2)%3 == (c-1)%3

        const uint32_t As = sbase + (c % GSTAGES) * STAGE_BYTES;
        const uint32_t Bs = As + 16384;
#pragma unroll
        for (int ks = 0; ks < 4; ks++) {
            uint32_t a[2][4], b[4][4];
#pragma unroll
            for (int i = 0; i < 2; i++) {
                const int row = wm * 32 + i * 16 + r8 + (quad & 1) * 8;
                const int cb  = ks * 32 + (quad >> 1) * 16;
                ldm_x4(a[i], As + SWZ128((uint32_t)(row * 128 + cb)));
            }
#pragma unroll
            for (int j = 0; j < 4; j++) {
                const int row = wn * 64 + j * 16 + r8 + (quad >> 1) * 8;
                const int cb  = ks * 32 + (quad & 1) * 16;
                ldm_x4(b[j], Bs + SWZ128((uint32_t)(row * 128 + cb)));
            }
#pragma unroll
            for (int i = 0; i < 2; i++)
#pragma unroll
                for (int j = 0; j < 4; j++) {
                    mma16816(acc[i][2 * j],     a[i][0], a[i][1], a[i][2], a[i][3], b[j][0], b[j][1]);
                    mma16816(acc[i][2 * j + 1], a[i][0], a[i][1], a[i][2], a[i][3], b[j][2], b[j][3]);
                }
        }
    }

    // ---- epilogue: C fragments -> global fp32 ----
    const int erow  = lane >> 2;
    const int ecol2 = (lane & 3) * 2;
#pragma unroll
    for (int i = 0; i < 2; i++)
#pragma unroll
        for (int f = 0; f < 8; f++) {
            float* p0 = C + (size_t)(m0 + wm * 32 + i * 16 + erow) * 1024
                          + n0 + wn * 64 + f * 8 + ecol2;
            *(float2*)p0            = make_float2(acc[i][f][0], acc[i][f][1]);
            *(float2*)(p0 + 8*1024) = make_float2(acc[i][f][2], acc[i][f][3]);
        }
}

// ---------------- cosine-norm + scale + rotary + bf16 split ---------------------
__global__ __launch_bounds__(512) void normrope_kernel(const float* __restrict__ s_qk)
{
    const int t    = blockIdx.x;
    const int h    = threadIdx.x >> 5;
    const int lane = threadIdx.x & 31;

    float c, s;
    if (lane < 16) {
        float theta = (float)t * FREQ16[lane];
        sincosf(theta, &s, &c);
    } else { c = 1.0f; s = 0.0f; }

    const float sc1 = s_qk[h * HD + lane]      * 32.0f;
    const float sc2 = s_qk[h * HD + lane + 32] * 32.0f;

    const size_t base = (size_t)t * DIM_ + h * HD;

    const float* inp[2] = {g_q + base, g_k + base};
    __nv_bfloat16* oh[2] = {g_qh + base, g_kh + base};
    __nv_bfloat16* ol[2] = {g_ql + base, g_kl + base};
#pragma unroll
    for (int w = 0; w < 2; w++) {
        const float* p = inp[w];
        float v1 = p[lane];
        float v2 = p[lane + 32];
        float ss = v1 * v1 + v2 * v2;
#pragma unroll
        for (int o = 16; o > 0; o >>= 1)
            ss += __shfl_xor_sync(0xffffffffu, ss, o);
        float rn = rsqrtf(ss + 1e-12f);
        v1 *= rn * sc1;
        v2 *= rn * sc2;
        float y1 = v1 * c + v2 * s;
        float y2 = v2 * c - v1 * s;
        __nv_bfloat16 h1 = __float2bfloat16(y1);
        __nv_bfloat16 h2 = __float2bfloat16(y2);
        oh[w][lane]      = h1;
        oh[w][lane + 32] = h2;
        ol[w][lane]      = __float2bfloat16(y1 - __bfloat162float(h1));
        ol[w][lane + 32] = __float2bfloat16(y2 - __bfloat162float(h2));
    }
    {
        float v1 = g_v[base + lane];
        float v2 = g_v[base + lane + 32];
        __nv_bfloat16 h1 = __float2bfloat16(v1);
        __nv_bfloat16 h2 = __float2bfloat16(v2);
        g_vh[base + lane]      = h1;
        g_vh[base + lane + 32] = h2;
        g_vl[base + lane]      = __float2bfloat16(v1 - __bfloat162float(h1));
        g_vl[base + lane + 32] = __float2bfloat16(v2 - __bfloat162float(h2));
    }
}

// ---------------- register-resident flash attention (raw mma.sync) --------------
#define ALD 72
#define ATT_SMEM (4 * 64 * ALD * 2)     // Kh,Kl,VTh,VTl bf16 = 36864 B

__global__ __launch_bounds__(128) void attn_mma()
{
    extern __shared__ __nv_bfloat16 smx[];
    __nv_bfloat16* Kh  = smx;
    __nv_bfloat16* Kl  = smx + 64 * ALD;
    __nv_bfloat16* VTh = smx + 2 * 64 * ALD;   // [hd][key]
    __nv_bfloat16* VTl = smx + 3 * 64 * ALD;

    const int qb   = 31 - (int)blockIdx.x;
    const int h    = blockIdx.y;
    const int tid  = threadIdx.x;
    const int wid  = tid >> 5;
    const int lane = tid & 31;
    const int lr   = lane >> 2;
    const int lc   = lane & 3;

    const size_t qrow0 = (size_t)(qb * 64 + wid * 16 + lr) * DIM_ + h * HD;
    const size_t qrow8 = qrow0 + 8 * DIM_;
    uint32_t qa_h[4][4], qa_l[4][4];
#pragma unroll
    for (int t = 0; t < 4; t++) {
        const int c0 = t * 16 + 2 * lc;
        qa_h[t][0] = *(const uint32_t*)(g_qh + qrow0 + c0);
        qa_h[t][1] = *(const uint32_t*)(g_qh + qrow8 + c0);
        qa_h[t][2] = *(const uint32_t*)(g_qh + qrow0 + c0 + 8);
        qa_h[t][3] = *(const uint32_t*)(g_qh + qrow8 + c0 + 8);
        qa_l[t][0] = *(const uint32_t*)(g_ql + qrow0 + c0);
        qa_l[t][1] = *(const uint32_t*)(g_ql + qrow8 + c0);
        qa_l[t][2] = *(const uint32_t*)(g_ql + qrow0 + c0 + 8);
        qa_l[t][3] = *(const uint32_t*)(g_ql + qrow8 + c0 + 8);
    }

    float ofr[8][4];
#pragma unroll
    for (int j = 0; j < 8; j++)
#pragma unroll
        for (int q = 0; q < 4; q++) ofr[j][q] = 0.0f;
    float m0 = -1e30f, m1 = -1e30f, l0 = 0.0f, l1 = 0.0f;

    const int gr0 = qb * 64 + wid * 16 + lr;
    const int gr8 = gr0 + 8;

    for (int kb = 0; kb <= qb; kb++) {
        __syncthreads();
        {
            const __nv_bfloat16* GKh = g_kh + (size_t)(kb * 64) * DIM_ + h * HD;
            const __nv_bfloat16* GKl = g_kl + (size_t)(kb * 64) * DIM_ + h * HD;
            const int r  = tid >> 1;
            const int cc = (tid & 1) * 32;
#pragma unroll
            for (int s = 0; s < 4; s++) {
                *(uint4*)(Kh + r * ALD + cc + s * 8) =
                    *(const uint4*)(GKh + (size_t)r * DIM_ + cc + s * 8);
                *(uint4*)(Kl + r * ALD + cc + s * 8) =
                    *(const uint4*)(GKl + (size_t)r * DIM_ + cc + s * 8);
            }
        }
        {
            const __nv_bfloat16* GVh = g_vh + (size_t)(kb * 64) * DIM_ + h * HD;
            const __nv_bfloat16* GVl = g_vl + (size_t)(kb * 64) * DIM_ + h * HD;
            const int k0 = (tid >> 2) * 2;
#pragma unroll
            for (int s = 0; s < 2; s++) {
                const int hb = (tid & 3) * 8 + s * 32;
                uint4 va = *(const uint4*)(GVh + (size_t)k0 * DIM_ + hb);
                uint4 vb = *(const uint4*)(GVh + (size_t)(k0 + 1) * DIM_ + hb);
                const ushort* pa = (const ushort*)&va;
                const ushort* pb = (const ushort*)&vb;
#pragma unroll
                for (int j = 0; j < 8; j++)
                    *(uint32_t*)(VTh + (hb + j) * ALD + k0) =
                        (uint32_t)pa[j] | ((uint32_t)pb[j] << 16);
                uint4 wa = *(const uint4*)(GVl + (size_t)k0 * DIM_ + hb);
                uint4 wb = *(const uint4*)(GVl + (size_t)(k0 + 1) * DIM_ + hb);
                const ushort* qa = (const ushort*)&wa;
                const ushort* qv = (const ushort*)&wb;
#pragma unroll
                for (int j = 0; j < 8; j++)
                    *(uint32_t*)(VTl + (hb + j) * ALD + k0) =
                        (uint32_t)qa[j] | ((uint32_t)qv[j] << 16);
            }
        }
        __syncthreads();

        float sfr[8][4];
#pragma unroll
        for (int j = 0; j < 8; j++)
#pragma unroll
            for (int q = 0; q < 4; q++) sfr[j][q] = 0.0f;

#pragma unroll
        for (int t = 0; t < 4; t++) {
#pragma unroll
            for (int j = 0; j < 8; j++) {
                const int boff = (j * 8 + lr) * ALD + t * 16 + 2 * lc;
                uint32_t bh0 = *(const uint32_t*)(Kh + boff);
                uint32_t bh1 = *(const uint32_t*)(Kh + boff + 8);
                uint32_t bl0 = *(const uint32_t*)(Kl + boff);
                uint32_t bl1 = *(const uint32_t*)(Kl + boff + 8);
                mma16816(sfr[j], qa_h[t][0], qa_h[t][1], qa_h[t][2], qa_h[t][3], bh0, bh1);
                mma16816(sfr[j], qa_h[t][0], qa_h[t][1], qa_h[t][2], qa_h[t][3], bl0, bl1);
                mma16816(sfr[j], qa_l[t][0], qa_l[t][1], qa_l[t][2], qa_l[t][3], bh0, bh1);
            }
        }

        const bool diag = (kb == qb);
#pragma unroll
        for (int j = 0; j < 8; j++) {
            const int gc = kb * 64 + j * 8 + 2 * lc;
            float v0 = sfr[j][0] * ATTN_SCALE;
            float v1 = sfr[j][1] * ATTN_SCALE;
            float v2 = sfr[j][2] * ATTN_SCALE;
            float v3 = sfr[j][3] * ATTN_SCALE;
            if (diag) {
                if (gc     > gr0) v0 = -1e30f;
                if (gc + 1 > gr0) v1 = -1e30f;
                if (gc     > gr8) v2 = -1e30f;
                if (gc + 1 > gr8) v3 = -1e30f;
            }
            sfr[j][0] = v0; sfr[j][1] = v1; sfr[j][2] = v2; sfr[j][3] = v3;
        }

        float mx0 = -1e30f, mx1 = -1e30f;
#pragma unroll
        for (int j = 0; j < 8; j++) {
            mx0 = fmaxf(mx0, fmaxf(sfr[j][0], sfr[j][1]));
            mx1 = fmaxf(mx1, fmaxf(sfr[j][2], sfr[j][3]));
        }
        mx0 = fmaxf(mx0, __shfl_xor_sync(0xffffffffu, mx0, 1));
        mx0 = fmaxf(mx0, __shfl_xor_sync(0xffffffffu, mx0, 2));
        mx1 = fmaxf(mx1, __shfl_xor_sync(0xffffffffu, mx1, 1));
        mx1 = fmaxf(mx1, __shfl_xor_sync(0xffffffffu, mx1, 2));
        const float mn0 = fmaxf(m0, mx0);
        const float mn1 = fmaxf(m1, mx1);
        const float cor0 = __expf(m0 - mn0);
        const float cor1 = __expf(m1 - mn1);
        m0 = mn0; m1 = mn1;
        float s0 = 0.0f, s1 = 0.0f;
#pragma unroll
        for (int j = 0; j < 8; j++) {
            sfr[j][0] = __expf(sfr[j][0] - mn0);
            sfr[j][1] = __expf(sfr[j][1] - mn0);
            sfr[j][2] = __expf(sfr[j][2] - mn1);
            sfr[j][3] = __expf(sfr[j][3] - mn1);
            s0 += sfr[j][0] + sfr[j][1];
            s1 += sfr[j][2] + sfr[j][3];
        }
        s0 += __shfl_xor_sync(0xffffffffu, s0, 1);
        s0 += __shfl_xor_sync(0xffffffffu, s0, 2);
        s1 += __shfl_xor_sync(0xffffffffu, s1, 1);
        s1 += __shfl_xor_sync(0xffffffffu, s1, 2);
        l0 = l0 * cor0 + s0;
        l1 = l1 * cor1 + s1;

#pragma unroll
        for (int j = 0; j < 8; j++) {
            ofr[j][0] *= cor0; ofr[j][1] *= cor0;
            ofr[j][2] *= cor1; ofr[j][3] *= cor1;
        }

#pragma unroll
        for (int u = 0; u < 4; u++) {
            __nv_bfloat16 b00 = __float2bfloat16(sfr[2*u][0]);
            __nv_bfloat16 b01 = __float2bfloat16(sfr[2*u][1]);
            __nv_bfloat16 b02 = __float2bfloat16(sfr[2*u][2]);
            __nv_bfloat16 b03 = __float2bfloat16(sfr[2*u][3]);
            __nv_bfloat16 b10 = __float2bfloat16(sfr[2*u+1][0]);
            __nv_bfloat16 b11 = __float2bfloat16(sfr[2*u+1][1]);
            __nv_bfloat16 b12 = __float2bfloat16(sfr[2*u+1][2]);
            __nv_bfloat16 b13 = __float2bfloat16(sfr[2*u+1][3]);
            uint32_t pah0 = pack_bf16(b00, b01);
            uint32_t pah1 = pack_bf16(b02, b03);
            uint32_t pah2 = pack_bf16(b10, b11);
            uint32_t pah3 = pack_bf16(b12, b13);
            uint32_t pal0 = pack_bf16(__float2bfloat16(sfr[2*u][0]   - __bfloat162float(b00)),
                                      __float2bfloat16(sfr[2*u][1]   - __bfloat162float(b01)));
            uint32_t pal1 = pack_bf16(__float2bfloat16(sfr[2*u][2]   - __bfloat162float(b02)),
                                      __float2bfloat16(sfr[2*u][3]   - __bfloat162float(b03)));
            uint32_t pal2 = pack_bf16(__float2bfloat16(sfr[2*u+1][0] - __bfloat162float(b10)),
                                      __float2bfloat16(sfr[2*u+1][1] - __bfloat162float(b11)));
            uint32_t pal3 = pack_bf16(__float2bfloat16(sfr[2*u+1][2] - __bfloat162float(b12)),
                                      __float2bfloat16(sfr[2*u+1][3] - __bfloat162float(b13)));
#pragma unroll
            for (int j2 = 0; j2 < 8; j2++) {
                const int boff = (j2 * 8 + lr) * ALD + u * 16 + 2 * lc;
                uint32_t bh0 = *(const uint32_t*)(VTh + boff);
                uint32_t bh1 = *(const uint32_t*)(VTh + boff + 8);
                uint32_t bl0 = *(const uint32_t*)(VTl + boff);
                uint32_t bl1 = *(const uint32_t*)(VTl + boff + 8);
                mma16816(ofr[j2], pah0, pah1, pah2, pah3, bh0, bh1);
                mma16816(ofr[j2], pah0, pah1, pah2, pah3, bl0, bl1);
                mma16816(ofr[j2], pal0, pal1, pal2, pal3, bh0, bh1);
            }
        }
    }

    const float inv0 = 1.0f / l0;
    const float inv1 = 1.0f / l1;
    float* Y0 = g_y + (size_t)gr0 * DIM_ + h * HD;
    float* Y8 = g_y + (size_t)gr8 * DIM_ + h * HD;
#pragma unroll
    for (int j2 = 0; j2 < 8; j2++) {
        const int cc = j2 * 8 + 2 * lc;
        *(float2*)(Y0 + cc) = make_float2(ofr[j2][0] * inv0, ofr[j2][1] * inv0);
        *(float2*)(Y8 + cc) = make_float2(ofr[j2][2] * inv1, ofr[j2][3] * inv1);
    }
}

// ---------------- launcher ------------------------------------------------------
extern "C" void kernel_launch(void* const* d_in, const int* in_sizes, int n_in,
                              void* d_out, int out_size)
{
    const float* x    = (const float*)d_in[0];
    const float* Wq   = (const float*)d_in[1];
    const float* Wk   = (const float*)d_in[2];
    const float* Wv   = (const float*)d_in[3];
    const float* Wo   = (const float*)d_in[4];
    const float* s_qk = (const float*)d_in[5];
    float* out = (float*)d_out;

    cudaFuncSetAttribute(gemm_mma, cudaFuncAttributeMaxDynamicSharedMemorySize,
                         GEMM_SMEM);

    // operand prep
    split_kernel<<<2048, 256>>>(x, 0);
    wconv_kernel<<<dim3(32, 32, 4), 256>>>(Wq, Wk, Wv, Wo);

    // QKV projections (split-bf16, logical K'=3072, cp.async + ldmatrix + mma)
    gemm_mma<<<dim3(8, 16, 3), 256, GEMM_SMEM>>>(0, nullptr);

    // norm + rope + bf16 split for attention
    normrope_kernel<<<T_LEN, 512>>>(s_qk);

    // register-resident flash attention
    attn_mma<<<dim3(32, NHEAD), 128, ATT_SMEM>>>();

    // output projection
    split_kernel<<<2048, 256>>>(nullptr, 1);
    gemm_mma<<<dim3(8, 16, 1), 256, GEMM_SMEM>>>(1, out);
}

// round 11
// speedup vs baseline: 3.5319x; 1.1896x over previous
#include <cuda_runtime.h>
#include <cuda_bf16.h>
#include <math.h>
#include <stdint.h>

#define T_LEN 2048
#define DIM_  1024
#define NHEAD 16
#define HD    64
#define ATTN_SCALE 0.12f

// ---------------- scratch (static device memory; no allocations) ----------------
__device__ float g_q[T_LEN * DIM_];
__device__ float g_k[T_LEN * DIM_];
__device__ float g_v[T_LEN * DIM_];
// split-bf16 operands for GEMMs: [.,0:1024)=hi, [.,1024:2048)=lo
__device__ __nv_bfloat16 g_abig[T_LEN * 2048];
__device__ __nv_bfloat16 g_ybig[T_LEN * 2048];
__device__ __nv_bfloat16 g_wt[4][1024 * 2048];
// split-bf16 q/k/v for attention (post norm+rope), layout [t][1024]
__device__ __nv_bfloat16 g_qh[T_LEN * DIM_], g_ql[T_LEN * DIM_];
__device__ __nv_bfloat16 g_kh[T_LEN * DIM_], g_kl[T_LEN * DIM_];
__device__ __nv_bfloat16 g_vh[T_LEN * DIM_], g_vl[T_LEN * DIM_];

// rotary freqs (fp32 of 2^(-2i/3), matches (1/1024)^(i/15) computed in double)
__constant__ float FREQ16[16] = {
    1.0f, 0.6299605249474366f, 0.3968502629920499f, 0.25f,
    0.15749013123685915f, 0.09921256574801247f, 0.0625f, 0.03937253280921479f,
    0.024803141437003118f, 0.015625f, 0.009843133202303698f, 0.0062007853592507794f,
    0.00390625f, 0.0024607833005759246f, 0.0015501963398126949f, 0.0009765625f
};

// ---------------- PTX helpers ----------------------------------------------------
__device__ __forceinline__ uint32_t smem_u32(const void* p) {
    uint32_t a;
    asm("{ .reg .u64 t; cvta.to.shared.u64 t, %1; cvt.u32.u64 %0, t; }" : "=r"(a) : "l"(p));
    return a;
}
__device__ __forceinline__ void mma16816(float c[4],
                                         uint32_t a0, uint32_t a1, uint32_t a2, uint32_t a3,
                                         uint32_t b0, uint32_t b1)
{
    asm volatile("mma.sync.aligned.m16n8k16.row.col.f32.bf16.bf16.f32 "
                 "{%0,%1,%2,%3}, {%4,%5,%6,%7}, {%8,%9}, {%0,%1,%2,%3};"
                 : "+f"(c[0]), "+f"(c[1]), "+f"(c[2]), "+f"(c[3])
                 : "r"(a0), "r"(a1), "r"(a2), "r"(a3), "r"(b0), "r"(b1));
}
__device__ __forceinline__ void ldm_x4(uint32_t r[4], uint32_t addr) {
    asm volatile("ldmatrix.sync.aligned.m8n8.x4.shared.b16 {%0,%1,%2,%3}, [%4];"
                 : "=r"(r[0]), "=r"(r[1]), "=r"(r[2]), "=r"(r[3]) : "r"(addr));
}
__device__ __forceinline__ void ldm_x4_t(uint32_t r[4], uint32_t addr) {
    asm volatile("ldmatrix.sync.aligned.m8n8.x4.trans.shared.b16 {%0,%1,%2,%3}, [%4];"
                 : "=r"(r[0]), "=r"(r[1]), "=r"(r[2]), "=r"(r[3]) : "r"(addr));
}
__device__ __forceinline__ uint32_t pack_bf16(__nv_bfloat16 lo, __nv_bfloat16 hi)
{
    __nv_bfloat162 t; t.x = lo; t.y = hi;
    return *(uint32_t*)&t;
}
#define CP_ASYNC16(dst, src) \
    asm volatile("cp.async.cg.shared.global [%0], [%1], 16;" :: "r"(dst), "l"(src))
#define CP_COMMIT()  asm volatile("cp.async.commit_group;" ::: "memory")
#define CP_WAIT1()   asm volatile("cp.async.wait_group 1;" ::: "memory")
#define CP_WAIT0()   asm volatile("cp.async.wait_group 0;" ::: "memory")
#define SWZ128(o)    ((o) ^ (((o) >> 3) & 0x70))

// ---------------- split conversion (x -> hi|lo bf16) ----------------------------
__global__ __launch_bounds__(256) void split_kernel(const float* __restrict__ xin)
{
    int idx = blockIdx.x * 256 + threadIdx.x;
    float4 v = ((const float4*)xin)[idx];
    int m  = idx >> 8;
    int c0 = (idx & 255) << 2;
    __nv_bfloat16 h0 = __float2bfloat16(v.x), h1 = __float2bfloat16(v.y);
    __nv_bfloat16 h2 = __float2bfloat16(v.z), h3 = __float2bfloat16(v.w);
    __nv_bfloat16 l0 = __float2bfloat16(v.x - __bfloat162float(h0));
    __nv_bfloat16 l1 = __float2bfloat16(v.y - __bfloat162float(h1));
    __nv_bfloat16 l2 = __float2bfloat16(v.z - __bfloat162float(h2));
    __nv_bfloat16 l3 = __float2bfloat16(v.w - __bfloat162float(h3));
    __nv_bfloat16* po = g_abig + (size_t)m * 2048 + c0;
    po[0] = h0; po[1] = h1; po[2] = h2; po[3] = h3;
    po[1024] = l0; po[1025] = l1; po[1026] = l2; po[1027] = l3;
}

// ---------------- weight transpose + split: W[k][n] -> WT[n][k_hi | k_lo] -------
__global__ __launch_bounds__(256) void wconv_kernel(const float* __restrict__ Wq,
                                                    const float* __restrict__ Wk,
                                                    const float* __restrict__ Wv,
                                                    const float* __restrict__ Wo)
{
    __shared__ float tile[32][33];
    const int z = blockIdx.z;
    const float* W = (z == 0) ? Wq : (z == 1) ? Wk : (z == 2) ? Wv : Wo;
    __nv_bfloat16* WT = g_wt[z];
    const int tx = threadIdx.x & 31, ty = threadIdx.x >> 5;
    const int n  = blockIdx.x * 32 + tx;
    const int k0 = blockIdx.y * 32;
#pragma unroll
    for (int i = 0; i < 4; i++)
        tile[ty + i * 8][tx] = W[(size_t)(k0 + ty + i * 8) * 1024 + n];
    __syncthreads();
#pragma unroll
    for (int i = 0; i < 4; i++) {
        float v = tile[tx][ty + i * 8];
        __nv_bfloat16 hi = __float2bfloat16(v);
        __nv_bfloat16 lo = __float2bfloat16(v - __bfloat162float(hi));
        size_t base = (size_t)(blockIdx.x * 32 + ty + i * 8) * 2048 + k0 + tx;
        WT[base]        = hi;
        WT[base + 1024] = lo;
    }
}

// ---------------- raw-mma split-bf16 GEMM (R9, passing) -------------------------
#define GEMM_NCHUNK 48
#define GSTAGES 3
#define STAGE_BYTES 32768
#define GEMM_SMEM (GSTAGES * STAGE_BYTES)

__global__ __launch_bounds__(256, 2) void gemm_mma(int proj, float* __restrict__ outp)
{
    extern __shared__ char smg[];
    const uint32_t sbase = smem_u32(smg);
    const int tid  = threadIdx.x;
    const int wid  = tid >> 5;
    const int lane = tid & 31;
    const int n0 = blockIdx.x * 128;
    const int m0 = blockIdx.y * 128;
    const int z  = blockIdx.z;

    const __nv_bfloat16* A  = proj ? g_ybig : g_abig;
    const __nv_bfloat16* Bt = proj ? g_wt[3] : g_wt[z];
    float* C = proj ? outp : (z == 0 ? g_q : z == 1 ? g_k : g_v);

    const __nv_bfloat16* Ag = A  + (size_t)m0 * 2048;
    const __nv_bfloat16* Bg = Bt + (size_t)n0 * 2048;

    const int wm = wid >> 1;
    const int wn = wid & 1;
    const int quad = lane >> 3;
    const int r8   = lane & 7;

    float acc[2][8][4];
#pragma unroll
    for (int i = 0; i < 2; i++)
#pragma unroll
        for (int f = 0; f < 8; f++)
#pragma unroll
            for (int q = 0; q < 4; q++) acc[i][f][q] = 0.0f;

    auto load_chunk = [&](int cn) {
        const int part = cn >> 4, sub = cn & 15;
        const int ka = (part == 2 ? 1024 : 0) + sub * 64;
        const int kb = (part == 1 ? 1024 : 0) + sub * 64;
        const uint32_t As = sbase + (cn % GSTAGES) * STAGE_BYTES;
        const uint32_t Bs = As + 16384;
#pragma unroll
        for (int s = 0; s < 4; s++) {
            const int idx = tid + s * 256;
            const int row = idx >> 3, g = idx & 7;
            const uint32_t off = SWZ128((uint32_t)(row * 128 + g * 16));
            CP_ASYNC16(As + off, (const void*)(Ag + (size_t)row * 2048 + ka + g * 8));
            CP_ASYNC16(Bs + off, (const void*)(Bg + (size_t)row * 2048 + kb + g * 8));
        }
        CP_COMMIT();
    };

    load_chunk(0);
    load_chunk(1);

    for (int c = 0; c < GEMM_NCHUNK; c++) {
        if (c == GEMM_NCHUNK - 1) CP_WAIT0(); else CP_WAIT1();
        __syncthreads();
        if (c + 2 < GEMM_NCHUNK) load_chunk(c + 2);

        const uint32_t As = sbase + (c % GSTAGES) * STAGE_BYTES;
        const uint32_t Bs = As + 16384;
#pragma unroll
        for (int ks = 0; ks < 4; ks++) {
            uint32_t a[2][4], b[4][4];
#pragma unroll
            for (int i = 0; i < 2; i++) {
                const int row = wm * 32 + i * 16 + r8 + (quad & 1) * 8;
                const int cb  = ks * 32 + (quad >> 1) * 16;
                ldm_x4(a[i], As + SWZ128((uint32_t)(row * 128 + cb)));
            }
#pragma unroll
            for (int j = 0; j < 4; j++) {
                const int row = wn * 64 + j * 16 + r8 + (quad >> 1) * 8;
                const int cb  = ks * 32 + (quad & 1) * 16;
                ldm_x4(b[j], Bs + SWZ128((uint32_t)(row * 128 + cb)));
            }
#pragma unroll
            for (int i = 0; i < 2; i++)
#pragma unroll
                for (int j = 0; j < 4; j++) {
                    mma16816(acc[i][2 * j],     a[i][0], a[i][1], a[i][2], a[i][3], b[j][0], b[j][1]);
                    mma16816(acc[i][2 * j + 1], a[i][0], a[i][1], a[i][2], a[i][3], b[j][2], b[j][3]);
                }
        }
    }

    const int erow  = lane >> 2;
    const int ecol2 = (lane & 3) * 2;
#pragma unroll
    for (int i = 0; i < 2; i++)
#pragma unroll
        for (int f = 0; f < 8; f++) {
            float* p0 = C + (size_t)(m0 + wm * 32 + i * 16 + erow) * 1024
                          + n0 + wn * 64 + f * 8 + ecol2;
            *(float2*)p0            = make_float2(acc[i][f][0], acc[i][f][1]);
            *(float2*)(p0 + 8*1024) = make_float2(acc[i][f][2], acc[i][f][3]);
        }
}

// ---------------- cosine-norm + scale + rotary + bf16 split ---------------------
__global__ __launch_bounds__(512) void normrope_kernel(const float* __restrict__ s_qk)
{
    const int t    = blockIdx.x;
    const int h    = threadIdx.x >> 5;
    const int lane = threadIdx.x & 31;

    float c, s;
    if (lane < 16) {
        float theta = (float)t * FREQ16[lane];
        sincosf(theta, &s, &c);
    } else { c = 1.0f; s = 0.0f; }

    const float sc1 = s_qk[h * HD + lane]      * 32.0f;
    const float sc2 = s_qk[h * HD + lane + 32] * 32.0f;

    const size_t base = (size_t)t * DIM_ + h * HD;

    const float* inp[2] = {g_q + base, g_k + base};
    __nv_bfloat16* oh[2] = {g_qh + base, g_kh + base};
    __nv_bfloat16* ol[2] = {g_ql + base, g_kl + base};
#pragma unroll
    for (int w = 0; w < 2; w++) {
        const float* p = inp[w];
        float v1 = p[lane];
        float v2 = p[lane + 32];
        float ss = v1 * v1 + v2 * v2;
#pragma unroll
        for (int o = 16; o > 0; o >>= 1)
            ss += __shfl_xor_sync(0xffffffffu, ss, o);
        float rn = rsqrtf(ss + 1e-12f);
        v1 *= rn * sc1;
        v2 *= rn * sc2;
        float y1 = v1 * c + v2 * s;
        float y2 = v2 * c - v1 * s;
        __nv_bfloat16 h1 = __float2bfloat16(y1);
        __nv_bfloat16 h2 = __float2bfloat16(y2);
        oh[w][lane]      = h1;
        oh[w][lane + 32] = h2;
        ol[w][lane]      = __float2bfloat16(y1 - __bfloat162float(h1));
        ol[w][lane + 32] = __float2bfloat16(y2 - __bfloat162float(h2));
    }
    {
        float v1 = g_v[base + lane];
        float v2 = g_v[base + lane + 32];
        __nv_bfloat16 h1 = __float2bfloat16(v1);
        __nv_bfloat16 h2 = __float2bfloat16(v2);
        g_vh[base + lane]      = h1;
        g_vh[base + lane + 32] = h2;
        g_vl[base + lane]      = __float2bfloat16(v1 - __bfloat162float(h1));
        g_vl[base + lane + 32] = __float2bfloat16(v2 - __bfloat162float(h2));
    }
}

// ---------------- pipelined flash attention (cp.async + ldmatrix) ---------------
// grid (32 qb, 16 h), 128 thr. Warp owns 16 q rows x all 64 keys.
// Stage: Kh | Kl | Vh | Vl, each 64x64 bf16 (128B rows, SW128). 2 stages = 64KB.
// K B-frags via ldmatrix.x4; V B-frags via ldmatrix.x4.trans (no manual transpose).
// Epilogue writes hi/lo bf16 splits directly into g_ybig.
#define ATT_STAGE 32768
#define ATT_SMEM  (2 * ATT_STAGE)

__global__ __launch_bounds__(128) void attn_mma()
{
    extern __shared__ char sma[];
    const uint32_t sbase = smem_u32(sma);

    const int qb   = 31 - (int)blockIdx.x;
    const int h    = blockIdx.y;
    const int tid  = threadIdx.x;
    const int wid  = tid >> 5;
    const int lane = tid & 31;
    const int lr   = lane >> 2;
    const int lc   = lane & 3;

    const __nv_bfloat16* GKh0 = g_kh + h * HD;
    const __nv_bfloat16* GKl0 = g_kl + h * HD;
    const __nv_bfloat16* GVh0 = g_vh + h * HD;
    const __nv_bfloat16* GVl0 = g_vl + h * HD;

    // async tile loader: 512 granules per sub-tile, 4 sub-tiles
    auto load_tiles = [&](int kb, int stage) {
        const uint32_t sb = sbase + stage * ATT_STAGE;
        const size_t gbase = (size_t)(kb * 64) * DIM_;
#pragma unroll
        for (int i = 0; i < 4; i++) {
            const int idx = tid + i * 128;
            const int row = idx >> 3, g = idx & 7;
            const uint32_t off = SWZ128((uint32_t)(row * 128 + g * 16));
            const size_t goff = gbase + (size_t)row * DIM_ + g * 8;
            CP_ASYNC16(sb + off,          (const void*)(GKh0 + goff));
            CP_ASYNC16(sb + 8192 + off,   (const void*)(GKl0 + goff));
            CP_ASYNC16(sb + 16384 + off,  (const void*)(GVh0 + goff));
            CP_ASYNC16(sb + 24576 + off,  (const void*)(GVl0 + goff));
        }
        CP_COMMIT();
    };

    // ---- hoist Q A-fragments (hi/lo) from global ----
    const size_t qrow0 = (size_t)(qb * 64 + wid * 16 + lr) * DIM_ + h * HD;
    const size_t qrow8 = qrow0 + 8 * DIM_;
    uint32_t qa_h[4][4], qa_l[4][4];
#pragma unroll
    for (int t = 0; t < 4; t++) {
        const int c0 = t * 16 + 2 * lc;
        qa_h[t][0] = *(const uint32_t*)(g_qh + qrow0 + c0);
        qa_h[t][1] = *(const uint32_t*)(g_qh + qrow8 + c0);
        qa_h[t][2] = *(const uint32_t*)(g_qh + qrow0 + c0 + 8);
        qa_h[t][3] = *(const uint32_t*)(g_qh + qrow8 + c0 + 8);
        qa_l[t][0] = *(const uint32_t*)(g_ql + qrow0 + c0);
        qa_l[t][1] = *(const uint32_t*)(g_ql + qrow8 + c0);
        qa_l[t][2] = *(const uint32_t*)(g_ql + qrow0 + c0 + 8);
        qa_l[t][3] = *(const uint32_t*)(g_ql + qrow8 + c0 + 8);
    }

    load_tiles(0, 0);

    float ofr[8][4];
#pragma unroll
    for (int j = 0; j < 8; j++)
#pragma unroll
        for (int q = 0; q < 4; q++) ofr[j][q] = 0.0f;
    float m0 = -1e30f, m1 = -1e30f, l0 = 0.0f, l1 = 0.0f;

    const int gr0 = qb * 64 + wid * 16 + lr;
    const int gr8 = gr0 + 8;

    // ldmatrix lane addressing (common subexpressions)
    const int l7  = lane & 7;
    const int lk8 = (lane >> 4) * 8;          // +8 along "pair" dim (hi half)
    const int ld8 = ((lane >> 3) & 1) * 8;    // +8 along k dim

    for (int kb = 0; kb <= qb; kb++) {
        CP_WAIT0();
        __syncthreads();
        if (kb < qb) load_tiles(kb + 1, (kb + 1) & 1);

        const uint32_t sb  = sbase + (kb & 1) * ATT_STAGE;
        const uint32_t Khs = sb;
        const uint32_t Kls = sb + 8192;
        const uint32_t Vhs = sb + 16384;
        const uint32_t Vls = sb + 24576;

        // ---- S = Q K^T (3-term split) ----
        float sfr[8][4];
#pragma unroll
        for (int j = 0; j < 8; j++)
#pragma unroll
            for (int q = 0; q < 4; q++) sfr[j][q] = 0.0f;

#pragma unroll
        for (int t = 0; t < 4; t++) {
#pragma unroll
            for (int jp = 0; jp < 4; jp++) {
                // matrices: keys jp*16 + lk8 + l7, d = t*16 + ld8
                const uint32_t off = SWZ128((uint32_t)((jp * 16 + lk8 + l7) * 128
                                                       + (t * 16 + ld8) * 2));
                uint32_t kh[4], kl[4];
                ldm_x4(kh, Khs + off);
                ldm_x4(kl, Kls + off);
                mma16816(sfr[2*jp],   qa_h[t][0], qa_h[t][1], qa_h[t][2], qa_h[t][3], kh[0], kh[1]);
                mma16816(sfr[2*jp],   qa_h[t][0], qa_h[t][1], qa_h[t][2], qa_h[t][3], kl[0], kl[1]);
                mma16816(sfr[2*jp],   qa_l[t][0], qa_l[t][1], qa_l[t][2], qa_l[t][3], kh[0], kh[1]);
                mma16816(sfr[2*jp+1], qa_h[t][0], qa_h[t][1], qa_h[t][2], qa_h[t][3], kh[2], kh[3]);
                mma16816(sfr[2*jp+1], qa_h[t][0], qa_h[t][1], qa_h[t][2], qa_h[t][3], kl[2], kl[3]);
                mma16816(sfr[2*jp+1], qa_l[t][0], qa_l[t][1], qa_l[t][2], qa_l[t][3], kh[2], kh[3]);
            }
        }

        // ---- scale + causal mask ----
        const bool diag = (kb == qb);
#pragma unroll
        for (int j = 0; j < 8; j++) {
            const int gc = kb * 64 + j * 8 + 2 * lc;
            float v0 = sfr[j][0] * ATTN_SCALE;
            float v1 = sfr[j][1] * ATTN_SCALE;
            float v2 = sfr[j][2] * ATTN_SCALE;
            float v3 = sfr[j][3] * ATTN_SCALE;
            if (diag) {
                if (gc     > gr0) v0 = -1e30f;
                if (gc + 1 > gr0) v1 = -1e30f;
                if (gc     > gr8) v2 = -1e30f;
                if (gc + 1 > gr8) v3 = -1e30f;
            }
            sfr[j][0] = v0; sfr[j][1] = v1; sfr[j][2] = v2; sfr[j][3] = v3;
        }

        // ---- in-warp online softmax ----
        float mx0 = -1e30f, mx1 = -1e30f;
#pragma unroll
        for (int j = 0; j < 8; j++) {
            mx0 = fmaxf(mx0, fmaxf(sfr[j][0], sfr[j][1]));
            mx1 = fmaxf(mx1, fmaxf(sfr[j][2], sfr[j][3]));
        }
        mx0 = fmaxf(mx0, __shfl_xor_sync(0xffffffffu, mx0, 1));
        mx0 = fmaxf(mx0, __shfl_xor_sync(0xffffffffu, mx0, 2));
        mx1 = fmaxf(mx1, __shfl_xor_sync(0xffffffffu, mx1, 1));
        mx1 = fmaxf(mx1, __shfl_xor_sync(0xffffffffu, mx1, 2));
        const float mn0 = fmaxf(m0, mx0);
        const float mn1 = fmaxf(m1, mx1);
        const float cor0 = __expf(m0 - mn0);
        const float cor1 = __expf(m1 - mn1);
        m0 = mn0; m1 = mn1;
        float s0 = 0.0f, s1 = 0.0f;
#pragma unroll
        for (int j = 0; j < 8; j++) {
            sfr[j][0] = __expf(sfr[j][0] - mn0);
            sfr[j][1] = __expf(sfr[j][1] - mn0);
            sfr[j][2] = __expf(sfr[j][2] - mn1);
            sfr[j][3] = __expf(sfr[j][3] - mn1);
            s0 += sfr[j][0] + sfr[j][1];
            s1 += sfr[j][2] + sfr[j][3];
        }
        s0 += __shfl_xor_sync(0xffffffffu, s0, 1);
        s0 += __shfl_xor_sync(0xffffffffu, s0, 2);
        s1 += __shfl_xor_sync(0xffffffffu, s1, 1);
        s1 += __shfl_xor_sync(0xffffffffu, s1, 2);
        l0 = l0 * cor0 + s0;
        l1 = l1 * cor1 + s1;

#pragma unroll
        for (int j = 0; j < 8; j++) {
            ofr[j][0] *= cor0; ofr[j][1] *= cor0;
            ofr[j][2] *= cor1; ofr[j][3] *= cor1;
        }

        // ---- O += P V (3-term split); V B-frags via ldmatrix.trans ----
#pragma unroll
        for (int u = 0; u < 4; u++) {
            __nv_bfloat16 b00 = __float2bfloat16(sfr[2*u][0]);
            __nv_bfloat16 b01 = __float2bfloat16(sfr[2*u][1]);
            __nv_bfloat16 b02 = __float2bfloat16(sfr[2*u][2]);
            __nv_bfloat16 b03 = __float2bfloat16(sfr[2*u][3]);
            __nv_bfloat16 b10 = __float2bfloat16(sfr[2*u+1][0]);
            __nv_bfloat16 b11 = __float2bfloat16(sfr[2*u+1][1]);
            __nv_bfloat16 b12 = __float2bfloat16(sfr[2*u+1][2]);
            __nv_bfloat16 b13 = __float2bfloat16(sfr[2*u+1][3]);
            uint32_t pah0 = pack_bf16(b00, b01);
            uint32_t pah1 = pack_bf16(b02, b03);
            uint32_t pah2 = pack_bf16(b10, b11);
            uint32_t pah3 = pack_bf16(b12, b13);
            uint32_t pal0 = pack_bf16(__float2bfloat16(sfr[2*u][0]   - __bfloat162float(b00)),
                                      __float2bfloat16(sfr[2*u][1]   - __bfloat162float(b01)));
            uint32_t pal1 = pack_bf16(__float2bfloat16(sfr[2*u][2]   - __bfloat162float(b02)),
                                      __float2bfloat16(sfr[2*u][3]   - __bfloat162float(b03)));
            uint32_t pal2 = pack_bf16(__float2bfloat16(sfr[2*u+1][0] - __bfloat162float(b10)),
                                      __float2bfloat16(sfr[2*u+1][1] - __bfloat162float(b11)));
            uint32_t pal3 = pack_bf16(__float2bfloat16(sfr[2*u+1][2] - __bfloat162float(b12)),
                                      __float2bfloat16(sfr[2*u+1][3] - __bfloat162float(b13)));
#pragma unroll
            for (int jp = 0; jp < 4; jp++) {
                // matrices: keys u*16 + ld8 + l7, d = jp*16 + lk8
                const uint32_t off = SWZ128((uint32_t)((u * 16 + ld8 + l7) * 128
                                                       + (jp * 16 + lk8) * 2));
                uint32_t vh[4], vl[4];
                ldm_x4_t(vh, Vhs + off);
                ldm_x4_t(vl, Vls + off);
                mma16816(ofr[2*jp],   pah0, pah1, pah2, pah3, vh[0], vh[1]);
                mma16816(ofr[2*jp],   pah0, pah1, pah2, pah3, vl[0], vl[1]);
                mma16816(ofr[2*jp],   pal0, pal1, pal2, pal3, vh[0], vh[1]);
                mma16816(ofr[2*jp+1], pah0, pah1, pah2, pah3, vh[2], vh[3]);
                mma16816(ofr[2*jp+1], pah0, pah1, pah2, pah3, vl[2], vl[3]);
                mma16816(ofr[2*jp+1], pal0, pal1, pal2, pal3, vh[2], vh[3]);
            }
        }
    }

    // ---- epilogue: write hi/lo bf16 split of (O/l) straight into g_ybig ----
    const float inv0 = 1.0f / l0;
    const float inv1 = 1.0f / l1;
    __nv_bfloat16* Y0 = g_ybig + (size_t)gr0 * 2048 + h * HD;
    __nv_bfloat16* Y8 = g_ybig + (size_t)gr8 * 2048 + h * HD;
#pragma unroll
    for (int j2 = 0; j2 < 8; j2++) {
        const int cc = j2 * 8 + 2 * lc;
        float y0 = ofr[j2][0] * inv0, y1 = ofr[j2][1] * inv0;
        float y2 = ofr[j2][2] * inv1, y3 = ofr[j2][3] * inv1;
        __nv_bfloat16 h0 = __float2bfloat16(y0), h1 = __float2bfloat16(y1);
        __nv_bfloat16 h2 = __float2bfloat16(y2), h3 = __float2bfloat16(y3);
        *(uint32_t*)(Y0 + cc)        = pack_bf16(h0, h1);
        *(uint32_t*)(Y8 + cc)        = pack_bf16(h2, h3);
        *(uint32_t*)(Y0 + 1024 + cc) = pack_bf16(__float2bfloat16(y0 - __bfloat162float(h0)),
                                                 __float2bfloat16(y1 - __bfloat162float(h1)));
        *(uint32_t*)(Y8 + 1024 + cc) = pack_bf16(__float2bfloat16(y2 - __bfloat162float(h2)),
                                                 __float2bfloat16(y3 - __bfloat162float(h3)));
    }
}

// ---------------- launcher ------------------------------------------------------
extern "C" void kernel_launch(void* const* d_in, const int* in_sizes, int n_in,
                              void* d_out, int out_size)
{
    const float* x    = (const float*)d_in[0];
    const float* Wq   = (const float*)d_in[1];
    const float* Wk   = (const float*)d_in[2];
    const float* Wv   = (const float*)d_in[3];
    const float* Wo   = (const float*)d_in[4];
    const float* s_qk = (const float*)d_in[5];
    float* out = (float*)d_out;

    cudaFuncSetAttribute(gemm_mma, cudaFuncAttributeMaxDynamicSharedMemorySize,
                         GEMM_SMEM);
    cudaFuncSetAttribute(attn_mma, cudaFuncAttributeMaxDynamicSharedMemorySize,
                         ATT_SMEM);

    // operand prep
    split_kernel<<<2048, 256>>>(x);
    wconv_kernel<<<dim3(32, 32, 4), 256>>>(Wq, Wk, Wv, Wo);

    // QKV projections (split-bf16, logical K'=3072)
    gemm_mma<<<dim3(8, 16, 3), 256, GEMM_SMEM>>>(0, nullptr);

    // norm + rope + bf16 split for attention
    normrope_kernel<<<T_LEN, 512>>>(s_qk);

    // pipelined flash attention (epilogue feeds g_ybig directly)
    attn_mma<<<dim3(32, NHEAD), 128, ATT_SMEM>>>();

    // output projection
    gemm_mma<<<dim3(8, 16, 1), 256, GEMM_SMEM>>>(1, out);
}